// round 10
// baseline (speedup 1.0000x reference)
#include <cuda_runtime.h>
#include <math.h>

// Problem constants
#define MROWS  16384   // B*T*S = 32*512
#define DMODEL 768
#define SEQ    512
#define NHEAD  12
#define HDIM   64
#define NBATCH 384     // (B*T)*H = 32*12

// ---------------- scratch (static device memory; no allocation) --------------
__device__ float g_Q  [(size_t)NBATCH * SEQ * HDIM];   // [b*h][s][d] (pre-scaled, tf32-rounded)
__device__ float g_Kt [(size_t)NBATCH * HDIM * SEQ];   // [b*h][d][s] (tf32-rounded)
__device__ float g_V  [(size_t)NBATCH * SEQ * HDIM];   // [b*h][s][d] (tf32-rounded)
__device__ float g_CTX[(size_t)MROWS * DMODEL];        // [row][h*64+d] (tf32-rounded)
__device__ float g_Xr [(size_t)MROWS * DMODEL];        // tf32-rounded x
__device__ float g_Wr [(size_t)4 * DMODEL * DMODEL];   // tf32-rounded Wq,Wk,Wv,Wo

// ---------------- helpers ----------------
__device__ __forceinline__ unsigned f2tf(float f) {
    unsigned u;
    asm("cvt.rna.tf32.f32 %0, %1;" : "=r"(u) : "f"(f));
    return u;
}
__device__ __forceinline__ float f2tff(float f) { return __uint_as_float(f2tf(f)); }

__device__ __forceinline__ void cp16(unsigned dst, const void* src) {
    asm volatile("cp.async.ca.shared.global [%0], [%1], 16;" :: "r"(dst), "l"(src));
}

#define MMA_TF32(d, a, b)                                                          \
    asm volatile(                                                                  \
        "mma.sync.aligned.m16n8k8.row.col.f32.tf32.tf32.f32 "                      \
        "{%0,%1,%2,%3}, {%4,%5,%6,%7}, {%8,%9}, {%0,%1,%2,%3};"                    \
        : "+f"((d)[0]), "+f"((d)[1]), "+f"((d)[2]), "+f"((d)[3])                   \
        : "r"((a)[0]), "r"((a)[1]), "r"((a)[2]), "r"((a)[3]),                      \
          "r"((b)[0]), "r"((b)[1]))

// =============================================================================
// prep: tf32-round x and the 4 weight matrices into scratch.
// =============================================================================
#define XQUADS ((MROWS * DMODEL) / 4)
#define WQUADS ((DMODEL * DMODEL) / 4)
#define PREP_QUADS (XQUADS + 4 * WQUADS)

__global__ __launch_bounds__(256) void prep_round(
    const float* __restrict__ x,  const float* __restrict__ Wq,
    const float* __restrict__ Wk, const float* __restrict__ Wv,
    const float* __restrict__ Wo)
{
    int i = blockIdx.x * 256 + threadIdx.x;
    if (i >= PREP_QUADS) return;
    const float4* src;
    float4* dst;
    if (i < XQUADS) {
        src = (const float4*)x + i;
        dst = (float4*)g_Xr + i;
    } else {
        int j = i - XQUADS;
        int w = j / WQUADS, o = j - w * WQUADS;
        const float* ws = (w == 0) ? Wq : (w == 1) ? Wk : (w == 2) ? Wv : Wo;
        src = (const float4*)ws + o;
        dst = (float4*)(g_Wr + (size_t)w * DMODEL * DMODEL) + o;
    }
    float4 v = *src;
    v.x = f2tff(v.x); v.y = f2tff(v.y); v.z = f2tff(v.z); v.w = f2tff(v.w);
    *dst = v;
}

// scatter for projection GEMM epilogues (rounds for modes 0-2)
__device__ __forceinline__ void scatter(int mode, int m, int n, float v,
                                        float* __restrict__ out) {
    int bt = m >> 9, s = m & 511;
    int h = n >> 6, d = n & 63;
    if (mode == 0) {
        g_Q[((size_t)(bt * NHEAD + h) * SEQ + s) * HDIM + d] = f2tff(v * 0.125f);
    } else if (mode == 1) {
        g_Kt[((size_t)(bt * NHEAD + h) * HDIM + d) * SEQ + s] = f2tff(v);
    } else if (mode == 2) {
        g_V[((size_t)(bt * NHEAD + h) * SEQ + s) * HDIM + d] = f2tff(v);
    } else {
        out[(size_t)m * DMODEL + n] = v;
    }
}

// =============================================================================
// 128x128 tf32-MMA GEMM over K=768, cp.async double-buffered.
// v2: 128 threads = 4 warps, warp grid 2x2, warp tile 64x64 (32 acc chains).
// QKV fused via gridDim.z (mode = base_mode + blockIdx.z).
// =============================================================================
#define SA_STR 20
#define SB_STR 136
#define SA_SZ  (128 * SA_STR)
#define SB_SZ  (16 * SB_STR)

__global__ __launch_bounds__(128, 2) void gemm768(
    const float* __restrict__ bq, const float* __restrict__ bk,
    const float* __restrict__ bv, const float* __restrict__ bo,
    float* __restrict__ out, int base_mode)
{
    __shared__ float sA[2 * SA_SZ];
    __shared__ float sB[2 * SB_SZ];

    const int mode = base_mode + blockIdx.z;
    const float* __restrict__ bias =
        (mode == 0) ? bq : (mode == 1) ? bk : (mode == 2) ? bv : bo;
    const float* __restrict__ A = (mode == 3) ? (const float*)g_CTX : (const float*)g_Xr;
    const float* __restrict__ W = g_Wr + (size_t)mode * DMODEL * DMODEL;

    const int tid  = threadIdx.x;
    const int lane = tid & 31, warp = tid >> 5;
    const int wm = warp & 1, wn = warp >> 1;     // 2 x 2 warp grid
    const int grp = lane >> 2, tig = lane & 3;
    const int m0 = blockIdx.y * 128;
    const int n0 = blockIdx.x * 128;

    const unsigned sA_u32 = (unsigned)__cvta_generic_to_shared(sA);
    const unsigned sB_u32 = (unsigned)__cvta_generic_to_shared(sB);

    float acc[4][8][4];
#pragma unroll
    for (int i = 0; i < 4; i++)
#pragma unroll
        for (int j = 0; j < 8; j++)
#pragma unroll
            for (int e = 0; e < 4; e++) acc[i][j][e] = 0.0f;

#define G_LOAD_TILES(buf, k0)                                                     \
    {                                                                             \
        _Pragma("unroll")                                                         \
        for (int rep = 0; rep < 4; rep++) {                                       \
            int t = rep * 128 + tid;                                              \
            int r = t >> 2, c4 = (t & 3) * 4;                                     \
            cp16(sA_u32 + (unsigned)(((buf) * SA_SZ + r * SA_STR + c4) * 4),      \
                 A + (size_t)(m0 + r) * DMODEL + (k0) + c4);                      \
        }                                                                         \
        _Pragma("unroll")                                                         \
        for (int rep = 0; rep < 4; rep++) {                                       \
            int t = rep * 128 + tid;                                              \
            int r = t >> 5, c4 = (t & 31) * 4;                                    \
            cp16(sB_u32 + (unsigned)(((buf) * SB_SZ + r * SB_STR + c4) * 4),      \
                 W + (size_t)((k0) + r) * DMODEL + n0 + c4);                      \
        }                                                                         \
        asm volatile("cp.async.commit_group;" ::: "memory");                      \
    }

    G_LOAD_TILES(0, 0);

    int buf = 0;
    for (int k0 = 0; k0 < DMODEL; k0 += 16) {
        asm volatile("cp.async.wait_group 0;" ::: "memory");
        __syncthreads();
        if (k0 + 16 < DMODEL) G_LOAD_TILES(buf ^ 1, k0 + 16);

        const float* pA = sA + buf * SA_SZ;
        const float* pB = sB + buf * SB_SZ;
#pragma unroll
        for (int kk = 0; kk < 16; kk += 8) {
            unsigned af[4][4], bf[8][2];
#pragma unroll
            for (int mi = 0; mi < 4; mi++) {
                int m = wm * 64 + mi * 16 + grp;
                af[mi][0] = __float_as_uint(pA[m * SA_STR + kk + tig]);
                af[mi][1] = __float_as_uint(pA[(m + 8) * SA_STR + kk + tig]);
                af[mi][2] = __float_as_uint(pA[m * SA_STR + kk + tig + 4]);
                af[mi][3] = __float_as_uint(pA[(m + 8) * SA_STR + kk + tig + 4]);
            }
#pragma unroll
            for (int nj = 0; nj < 8; nj++) {
                int n = wn * 64 + nj * 8 + grp;
                bf[nj][0] = __float_as_uint(pB[(kk + tig) * SB_STR + n]);
                bf[nj][1] = __float_as_uint(pB[(kk + tig + 4) * SB_STR + n]);
            }
#pragma unroll
            for (int mi = 0; mi < 4; mi++)
#pragma unroll
                for (int nj = 0; nj < 8; nj++)
                    MMA_TF32(acc[mi][nj], af[mi], bf[nj]);
        }
        buf ^= 1;
    }

#pragma unroll
    for (int mi = 0; mi < 4; mi++) {
        int r0 = m0 + wm * 64 + mi * 16 + grp;
#pragma unroll
        for (int nj = 0; nj < 8; nj++) {
            int c0 = n0 + wn * 64 + nj * 8 + tig * 2;
            scatter(mode, r0,     c0,     acc[mi][nj][0] + bias[c0],     out);
            scatter(mode, r0,     c0 + 1, acc[mi][nj][1] + bias[c0 + 1], out);
            scatter(mode, r0 + 8, c0,     acc[mi][nj][2] + bias[c0],     out);
            scatter(mode, r0 + 8, c0 + 1, acc[mi][nj][3] + bias[c0 + 1], out);
        }
    }
#undef G_LOAD_TILES
}

// =============================================================================
// Fused attention: block = (head-batch, 64 q rows), 512 threads, 16 warps.
// NEW: block-sparse chunk skipping — per block, build the list of 128-key
// chunks any row actually attends (modality-summary test) and only compute
// those in both QK^T and PV phases.
// =============================================================================
#define OFF_Q     0                    // [q][kpacked] stride 68, 64x68
#define OFF_K     4352                 // 2 bufs of [k][n] stride 136, 64x136 each
#define OFF_P     4352                 // phase2: [q][kpacked] stride 140, 64x140
#define OFF_V     13312                // [s][d] stride 72, 128x72
#define OFF_MODS  22528
#define OFF_RED   23040                // 16 x 64
#define OFF_RMAX  24064
#define OFF_RINV  24128
#define OFF_CMSK  24192                // 4: per-chunk modality bitmask
#define OFF_RSUM  24196                // 2: row modality mask, row-has-latent
#define OFF_LIST  24198                // 4: needed chunk ids
#define OFF_NCH   24202                // 1
#define ATTN_SMEM_WORDS 24204
#define ATTN_SMEM_BYTES (ATTN_SMEM_WORDS * 4)

__device__ __forceinline__ int modbit(int m) {
    return (m == -1) ? 4 : (m == 0) ? 1 : (m == 1) ? 2 : 8;
}

extern __shared__ unsigned dsm[];

__global__ __launch_bounds__(512, 1) void attn_fused(
    const int* __restrict__ mods, const int* __restrict__ nlp)
{
    unsigned* sQ     = dsm + OFF_Q;
    float*    sK     = (float*)(dsm + OFF_K);
    unsigned* sP     = dsm + OFF_P;
    float*    sV     = (float*)(dsm + OFF_V);
    int*      s_mods = (int*)(dsm + OFF_MODS);
    float*    s_red  = (float*)(dsm + OFF_RED);
    float*    s_rmax = (float*)(dsm + OFF_RMAX);
    float*    s_rinv = (float*)(dsm + OFF_RINV);
    int*      s_cmsk = (int*)(dsm + OFF_CMSK);
    int*      s_rsum = (int*)(dsm + OFF_RSUM);
    int*      s_list = (int*)(dsm + OFF_LIST);
    int*      s_nch  = (int*)(dsm + OFF_NCH);

    const int tid  = threadIdx.x;
    const int lane = tid & 31, w = tid >> 5;
    const int grp  = lane >> 2, tig = lane & 3;
    const int wm = w & 1, wn = w >> 1;          // 2 x 8 warp grid
    const int batch = blockIdx.y;
    const int m0 = blockIdx.x * 64;
    const int bt = batch / NHEAD, h = batch % NHEAD;
    const int nlat = nlp ? *nlp : 32;

    const float* __restrict__ Qp = g_Q  + (size_t)batch * SEQ * HDIM;
    const float* __restrict__ Kp = g_Kt + (size_t)batch * HDIM * SEQ;
    const float* __restrict__ Vp = g_V  + (size_t)batch * SEQ * HDIM;
    const unsigned smem_u32 = (unsigned)__cvta_generic_to_shared(dsm);

    s_mods[tid] = mods[tid];
    {   // Q tile, packed-pair layout (values already tf32-rounded)
        int q = tid >> 3, j = tid & 7;
        const float* src = Qp + (size_t)(m0 + q) * HDIM + j * 8;
        float4 a = *(const float4*)src;
        float4 b = *(const float4*)(src + 4);
        unsigned* dst = sQ + q * 68 + j * 8;
        dst[0] = __float_as_uint(a.x); dst[1] = __float_as_uint(b.x);
        dst[2] = __float_as_uint(a.y); dst[3] = __float_as_uint(b.y);
        dst[4] = __float_as_uint(a.z); dst[5] = __float_as_uint(b.z);
        dst[6] = __float_as_uint(a.w); dst[7] = __float_as_uint(b.w);
    }
    __syncthreads();

    // ---------------- needed-chunk analysis ----------------
    if (tid < 4) {
        int cm = 0;
        for (int k = 0; k < 128; k++) cm |= modbit(s_mods[tid * 128 + k]);
        s_cmsk[tid] = cm;
    } else if (tid == 4) {
        int rm = 0, rl = 0;
        for (int r = 0; r < 64; r++) {
            int rg = m0 + r;
            if (rg < nlat) rl = 1;
            else rm |= modbit(s_mods[rg]);
        }
        s_rsum[0] = rm; s_rsum[1] = rl;
    }
    __syncthreads();
    if (tid == 0) {
        int n = 0;
        for (int c = 0; c < 4; c++)
            if (s_rsum[1] || (s_rsum[0] & s_cmsk[c])) s_list[n++] = c;
        *s_nch = n;
    }
    __syncthreads();
    const int nch = *s_nch;

#define LOAD_K(buf, c)                                                            \
    {                                                                             \
        _Pragma("unroll")                                                         \
        for (int rep = 0; rep < 4; rep++) {                                       \
            int idx = rep * 512 + tid;                                            \
            int r = idx >> 5, c4 = (idx & 31) * 4;                                \
            cp16(smem_u32 + (unsigned)((OFF_K + (buf) * 8704 + r * 136 + c4) * 4),\
                 Kp + (size_t)r * SEQ + (c) * 128 + c4);                          \
        }                                                                         \
        asm volatile("cp.async.commit_group;" ::: "memory");                      \
    }

    LOAD_K(0, s_list[0]);

    float S[4][2][2][4];
#pragma unroll
    for (int c = 0; c < 4; c++)
#pragma unroll
        for (int i = 0; i < 2; i++)
#pragma unroll
            for (int j = 0; j < 2; j++)
#pragma unroll
                for (int e = 0; e < 4; e++) S[c][i][j][e] = 0.0f;

    const unsigned* qr0 = sQ + (wm * 32 + grp) * 68 + 2 * tig;
    const unsigned* qr1 = sQ + (wm * 32 + grp + 8) * 68 + 2 * tig;
    const unsigned* qr2 = sQ + (wm * 32 + grp + 16) * 68 + 2 * tig;
    const unsigned* qr3 = sQ + (wm * 32 + grp + 24) * 68 + 2 * tig;
    const int bn0 = wn * 16 + grp;

    // ---------------- phase 1: S = Q @ K^T (needed chunks only) -------------
#pragma unroll
    for (int j = 0; j < 4; j++) {
        if (j >= nch) break;
        asm volatile("cp.async.wait_group 0;" ::: "memory");
        __syncthreads();
        if (j + 1 < nch) LOAD_K((j + 1) & 1, s_list[j + 1]);
        const float* pK = sK + (j & 1) * 8704;
#pragma unroll
        for (int kk = 0; kk < 64; kk += 8) {
            uint2 u00 = *(const uint2*)(qr0 + kk);
            uint2 u01 = *(const uint2*)(qr1 + kk);
            uint2 u10 = *(const uint2*)(qr2 + kk);
            uint2 u11 = *(const uint2*)(qr3 + kk);
            unsigned af0[4] = {u00.x, u01.x, u00.y, u01.y};
            unsigned af1[4] = {u10.x, u11.x, u10.y, u11.y};
            unsigned bf0[2] = { __float_as_uint(pK[(kk + tig) * 136 + bn0]),
                                __float_as_uint(pK[(kk + tig + 4) * 136 + bn0]) };
            unsigned bf1[2] = { __float_as_uint(pK[(kk + tig) * 136 + bn0 + 8]),
                                __float_as_uint(pK[(kk + tig + 4) * 136 + bn0 + 8]) };
            MMA_TF32(S[j][0][0], af0, bf0);
            MMA_TF32(S[j][0][1], af0, bf1);
            MMA_TF32(S[j][1][0], af1, bf0);
            MMA_TF32(S[j][1][1], af1, bf1);
        }
    }
#undef LOAD_K

    // ---------------- mask + softmax (needed chunks only) -------------------
    int rloc[4]; int mq[4]; bool lat[4]; float lm[4];
#pragma unroll
    for (int rr = 0; rr < 4; rr++) {
        int mi = rr >> 1, hh = rr & 1;
        rloc[rr] = wm * 32 + mi * 16 + hh * 8 + grp;
        int rg = m0 + rloc[rr];
        lat[rr] = (rg < nlat);
        mq[rr] = s_mods[rg];
        lm[rr] = -3.0e38f;
    }
#pragma unroll
    for (int j = 0; j < 4; j++) {
        if (j >= nch) break;
        int c = s_list[j];
#pragma unroll
        for (int nj = 0; nj < 2; nj++) {
            int k0 = c * 128 + wn * 16 + nj * 8 + 2 * tig;
            int md0 = s_mods[k0], md1 = s_mods[k0 + 1];
#pragma unroll
            for (int rr = 0; rr < 4; rr++) {
                int mi = rr >> 1, hh = rr & 1;
                float& s0 = S[j][mi][nj][hh * 2 + 0];
                float& s1 = S[j][mi][nj][hh * 2 + 1];
                if (!(lat[rr] || mq[rr] == md0)) s0 = -3.0e38f;
                if (!(lat[rr] || mq[rr] == md1)) s1 = -3.0e38f;
                lm[rr] = fmaxf(lm[rr], fmaxf(s0, s1));
            }
        }
    }
#pragma unroll
    for (int rr = 0; rr < 4; rr++) {
        lm[rr] = fmaxf(lm[rr], __shfl_xor_sync(0xffffffffu, lm[rr], 1));
        lm[rr] = fmaxf(lm[rr], __shfl_xor_sync(0xffffffffu, lm[rr], 2));
    }
    if (tig == 0) {
#pragma unroll
        for (int rr = 0; rr < 4; rr++) s_red[w * 64 + rloc[rr]] = lm[rr];
    }
    __syncthreads();
    if (tid < 64) {
        int wsel = tid >> 5;
        float m = -3.0e38f;
#pragma unroll
        for (int j = 0; j < 8; j++) m = fmaxf(m, s_red[(2 * j + wsel) * 64 + tid]);
        s_rmax[tid] = m;
    }
    __syncthreads();

    float rm[4], ls[4];
#pragma unroll
    for (int rr = 0; rr < 4; rr++) { rm[rr] = s_rmax[rloc[rr]]; ls[rr] = 0.0f; }
#pragma unroll
    for (int j = 0; j < 4; j++) {
        if (j >= nch) break;
#pragma unroll
        for (int nj = 0; nj < 2; nj++)
#pragma unroll
            for (int rr = 0; rr < 4; rr++) {
                int mi = rr >> 1, hh = rr & 1;
                float& s0 = S[j][mi][nj][hh * 2 + 0];
                float& s1 = S[j][mi][nj][hh * 2 + 1];
                s0 = __expf(s0 - rm[rr]);
                s1 = __expf(s1 - rm[rr]);
                ls[rr] += s0 + s1;
            }
    }
#pragma unroll
    for (int rr = 0; rr < 4; rr++) {
        ls[rr] += __shfl_xor_sync(0xffffffffu, ls[rr], 1);
        ls[rr] += __shfl_xor_sync(0xffffffffu, ls[rr], 2);
    }
    if (tig == 0) {
#pragma unroll
        for (int rr = 0; rr < 4; rr++) s_red[w * 64 + rloc[rr]] = ls[rr];
    }
    __syncthreads();
    if (tid < 64) {
        int wsel = tid >> 5;
        float s = 0.0f;
#pragma unroll
        for (int j = 0; j < 8; j++) s += s_red[(2 * j + wsel) * 64 + tid];
        s_rinv[tid] = 1.0f / s;
    }

    // ---------------- phase 2: O = P @ V (needed chunks only) ---------------
    float O0[4] = {0.0f, 0.0f, 0.0f, 0.0f};
    float O1[4] = {0.0f, 0.0f, 0.0f, 0.0f};
    const int vn = wn * 8 + grp;
    const unsigned* pr0 = sP + (wm * 32 + grp) * 140 + 2 * tig;
    const unsigned* pr1 = sP + (wm * 32 + grp + 8) * 140 + 2 * tig;
    const unsigned* pr2 = sP + (wm * 32 + grp + 16) * 140 + 2 * tig;
    const unsigned* pr3 = sP + (wm * 32 + grp + 24) * 140 + 2 * tig;

#pragma unroll
    for (int j = 0; j < 4; j++) {
        if (j >= nch) break;
        int c = s_list[j];
        __syncthreads();
#pragma unroll
        for (int rep = 0; rep < 4; rep++) {
            int idx = rep * 512 + tid;
            int r = idx >> 4, d4 = (idx & 15) * 4;
            cp16(smem_u32 + (unsigned)((OFF_V + r * 72 + d4) * 4),
                 Vp + (size_t)(c * 128 + r) * HDIM + d4);
        }
        asm volatile("cp.async.commit_group;" ::: "memory");
#pragma unroll
        for (int nj = 0; nj < 2; nj++)
#pragma unroll
            for (int b = 0; b < 2; b++) {
                int kl = wn * 16 + nj * 8 + 2 * tig + b;
                int pos = (kl >> 3) * 8 + (kl & 3) * 2 + ((kl >> 2) & 1);
#pragma unroll
                for (int rr = 0; rr < 4; rr++) {
                    int mi = rr >> 1, hh = rr & 1;
                    sP[rloc[rr] * 140 + pos] = f2tf(S[j][mi][nj][hh * 2 + b]);
                }
            }
        asm volatile("cp.async.wait_group 0;" ::: "memory");
        __syncthreads();
#pragma unroll
        for (int kk = 0; kk < 128; kk += 8) {
            uint2 u00 = *(const uint2*)(pr0 + kk);
            uint2 u01 = *(const uint2*)(pr1 + kk);
            uint2 u10 = *(const uint2*)(pr2 + kk);
            uint2 u11 = *(const uint2*)(pr3 + kk);
            unsigned af0[4] = {u00.x, u01.x, u00.y, u01.y};
            unsigned af1[4] = {u10.x, u11.x, u10.y, u11.y};
            unsigned bf[2] = { __float_as_uint(sV[(kk + tig) * 72 + vn]),
                               __float_as_uint(sV[(kk + tig + 4) * 72 + vn]) };
            MMA_TF32(O0, af0, bf);
            MMA_TF32(O1, af1, bf);
        }
    }

    // epilogue: normalize, tf32-round, write ctx
#pragma unroll
    for (int rr = 0; rr < 4; rr++) {
        int mi = rr >> 1, hh = rr & 1;
        const float* Osel = mi ? O1 : O0;
        float inv = s_rinv[rloc[rr]];
        float2 val;
        val.x = f2tff(Osel[hh * 2 + 0] * inv);
        val.y = f2tff(Osel[hh * 2 + 1] * inv);
        int d0 = wn * 8 + 2 * tig;
        *(float2*)(g_CTX + (size_t)(bt * SEQ + m0 + rloc[rr]) * DMODEL
                   + h * HDIM + d0) = val;
    }
}

// =============================================================================
extern "C" void kernel_launch(void* const* d_in, const int* in_sizes, int n_in,
                              void* d_out, int out_size)
{
    const float* x  = (const float*)d_in[0];
    const float* Wq = (const float*)d_in[1];
    const float* bq = (const float*)d_in[2];
    const float* Wk = (const float*)d_in[3];
    const float* bk = (const float*)d_in[4];
    const float* Wv = (const float*)d_in[5];
    const float* bv = (const float*)d_in[6];
    const float* Wo = (const float*)d_in[7];
    const float* bo = (const float*)d_in[8];
    const int* mods = (const int*)d_in[9];
    const int* nlp  = (n_in > 10) ? (const int*)d_in[10] : nullptr;
    float* out = (float*)d_out;

    cudaFuncSetAttribute(attn_fused, cudaFuncAttributeMaxDynamicSharedMemorySize,
                         ATTN_SMEM_BYTES);

    prep_round<<<(PREP_QUADS + 255) / 256, 256>>>(x, Wq, Wk, Wv, Wo);
    gemm768<<<dim3(6, 128, 3), 128>>>(bq, bk, bv, bo, nullptr, 0);   // Q,K,V fused
    attn_fused<<<dim3(SEQ / 64, NBATCH), 512, ATTN_SMEM_BYTES>>>(mods, nlp);
    gemm768<<<dim3(6, 128, 1), 128>>>(bq, bk, bv, bo, out, 3);       // out proj
}

// round 13
// speedup vs baseline: 1.2062x; 1.2062x over previous
#include <cuda_runtime.h>
#include <math.h>

// Problem constants
#define MROWS  16384   // B*T*S = 32*512
#define DMODEL 768
#define SEQ    512
#define NHEAD  12
#define HDIM   64
#define NBATCH 384     // (B*T)*H = 32*12

// ---------------- scratch (static device memory; no allocation) --------------
__device__ float g_Q  [(size_t)NBATCH * SEQ * HDIM];   // [b*h][s][d] (pre-scaled, tf32-rounded)
__device__ float g_Kt [(size_t)NBATCH * HDIM * SEQ];   // [b*h][d][s] (tf32-rounded)
__device__ float g_V  [(size_t)NBATCH * SEQ * HDIM];   // [b*h][s][d] (tf32-rounded)
__device__ float g_CTX[(size_t)MROWS * DMODEL];        // [row][h*64+d] (tf32-rounded)
__device__ float g_Xr [(size_t)MROWS * DMODEL];        // tf32-rounded x
__device__ float g_Wr [(size_t)4 * DMODEL * DMODEL];   // tf32-rounded Wq,Wk,Wv,Wo

// ---------------- helpers ----------------
__device__ __forceinline__ unsigned f2tf(float f) {
    unsigned u;
    asm("cvt.rna.tf32.f32 %0, %1;" : "=r"(u) : "f"(f));
    return u;
}
__device__ __forceinline__ float f2tff(float f) { return __uint_as_float(f2tf(f)); }

__device__ __forceinline__ void cp16(unsigned dst, const void* src) {
    asm volatile("cp.async.ca.shared.global [%0], [%1], 16;" :: "r"(dst), "l"(src));
}
__device__ __forceinline__ void wait_pending(int n) {
    if (n <= 0)      asm volatile("cp.async.wait_group 0;" ::: "memory");
    else if (n == 1) asm volatile("cp.async.wait_group 1;" ::: "memory");
    else if (n == 2) asm volatile("cp.async.wait_group 2;" ::: "memory");
    else             asm volatile("cp.async.wait_group 3;" ::: "memory");
}

#define MMA_TF32(d, a, b)                                                          \
    asm volatile(                                                                  \
        "mma.sync.aligned.m16n8k8.row.col.f32.tf32.tf32.f32 "                      \
        "{%0,%1,%2,%3}, {%4,%5,%6,%7}, {%8,%9}, {%0,%1,%2,%3};"                    \
        : "+f"((d)[0]), "+f"((d)[1]), "+f"((d)[2]), "+f"((d)[3])                   \
        : "r"((a)[0]), "r"((a)[1]), "r"((a)[2]), "r"((a)[3]),                      \
          "r"((b)[0]), "r"((b)[1]))

// =============================================================================
// prep: tf32-round x and the 4 weight matrices into scratch.
// =============================================================================
#define XQUADS ((MROWS * DMODEL) / 4)
#define WQUADS ((DMODEL * DMODEL) / 4)
#define PREP_QUADS (XQUADS + 4 * WQUADS)

__global__ __launch_bounds__(256) void prep_round(
    const float* __restrict__ x,  const float* __restrict__ Wq,
    const float* __restrict__ Wk, const float* __restrict__ Wv,
    const float* __restrict__ Wo)
{
    int i = blockIdx.x * 256 + threadIdx.x;
    if (i >= PREP_QUADS) return;
    const float4* src;
    float4* dst;
    if (i < XQUADS) {
        src = (const float4*)x + i;
        dst = (float4*)g_Xr + i;
    } else {
        int j = i - XQUADS;
        int w = j / WQUADS, o = j - w * WQUADS;
        const float* ws = (w == 0) ? Wq : (w == 1) ? Wk : (w == 2) ? Wv : Wo;
        src = (const float4*)ws + o;
        dst = (float4*)(g_Wr + (size_t)w * DMODEL * DMODEL) + o;
    }
    float4 v = *src;
    v.x = f2tff(v.x); v.y = f2tff(v.y); v.z = f2tff(v.z); v.w = f2tff(v.w);
    *dst = v;
}

// scatter for projection GEMM epilogues (rounds for modes 0-2)
__device__ __forceinline__ void scatter(int mode, int m, int n, float v,
                                        float* __restrict__ out) {
    int bt = m >> 9, s = m & 511;
    int h = n >> 6, d = n & 63;
    if (mode == 0) {
        g_Q[((size_t)(bt * NHEAD + h) * SEQ + s) * HDIM + d] = f2tff(v * 0.125f);
    } else if (mode == 1) {
        g_Kt[((size_t)(bt * NHEAD + h) * HDIM + d) * SEQ + s] = f2tff(v);
    } else if (mode == 2) {
        g_V[((size_t)(bt * NHEAD + h) * SEQ + s) * HDIM + d] = f2tff(v);
    } else {
        out[(size_t)m * DMODEL + n] = v;
    }
}

extern __shared__ unsigned dsm[];

// =============================================================================
// 128x128 tf32-MMA GEMM over K=768. v3: 256 threads, warp grid 2x4 (64x32),
// 4-stage cp.async pipeline (wait_group 2), dynamic smem, QKV via gridDim.z.
// stage layout (words): A [m][k] stride 20 (2560 w), B [k][n] stride 136 (2176 w)
// =============================================================================
#define GST_WORDS 4736
#define GD_BYTES  (4 * GST_WORDS * 4)   // 75776

__global__ __launch_bounds__(256, 2) void gemm768(
    const float* __restrict__ bq, const float* __restrict__ bk,
    const float* __restrict__ bv, const float* __restrict__ bo,
    float* __restrict__ out, int base_mode)
{
    float* sm = (float*)dsm;
    const int mode = base_mode + blockIdx.z;
    const float* __restrict__ bias =
        (mode == 0) ? bq : (mode == 1) ? bk : (mode == 2) ? bv : bo;
    const float* __restrict__ A = (mode == 3) ? (const float*)g_CTX : (const float*)g_Xr;
    const float* __restrict__ W = g_Wr + (size_t)mode * DMODEL * DMODEL;

    const int tid  = threadIdx.x;
    const int lane = tid & 31, warp = tid >> 5;
    const int wm = warp & 1, wn = warp >> 1;     // 2 x 4 warp grid
    const int grp = lane >> 2, tig = lane & 3;
    const int m0 = blockIdx.y * 128;
    const int n0 = blockIdx.x * 128;

    const unsigned s_u32 = (unsigned)__cvta_generic_to_shared(dsm);

    float acc[4][4][4];
#pragma unroll
    for (int i = 0; i < 4; i++)
#pragma unroll
        for (int j = 0; j < 4; j++)
#pragma unroll
            for (int e = 0; e < 4; e++) acc[i][j][e] = 0.0f;

#define G_LOAD(st, k0)                                                            \
    {                                                                             \
        _Pragma("unroll")                                                         \
        for (int rep = 0; rep < 2; rep++) {                                       \
            int t = rep * 256 + tid;                                              \
            int r = t >> 2, c4 = (t & 3) * 4;                                     \
            cp16(s_u32 + (unsigned)(((st) * GST_WORDS + r * 20 + c4) * 4),        \
                 A + (size_t)(m0 + r) * DMODEL + (k0) + c4);                      \
        }                                                                         \
        _Pragma("unroll")                                                         \
        for (int rep = 0; rep < 2; rep++) {                                       \
            int t = rep * 256 + tid;                                              \
            int r = t >> 5, c4 = (t & 31) * 4;                                    \
            cp16(s_u32 + (unsigned)(((st) * GST_WORDS + 2560 + r * 136 + c4) * 4),\
                 W + (size_t)((k0) + r) * DMODEL + n0 + c4);                      \
        }                                                                         \
        asm volatile("cp.async.commit_group;" ::: "memory");                      \
    }

    G_LOAD(0, 0);
    G_LOAD(1, 16);
    G_LOAD(2, 32);

    for (int ci = 0; ci < 48; ci++) {
        asm volatile("cp.async.wait_group 2;" ::: "memory");
        __syncthreads();
        if (ci + 3 < 48) G_LOAD((ci + 3) & 3, (ci + 3) * 16);

        const float* pA = sm + (ci & 3) * GST_WORDS;
        const float* pB = pA + 2560;
#pragma unroll
        for (int kk = 0; kk < 16; kk += 8) {
            unsigned af[4][4], bf[4][2];
#pragma unroll
            for (int mi = 0; mi < 4; mi++) {
                int m = wm * 64 + mi * 16 + grp;
                af[mi][0] = __float_as_uint(pA[m * 20 + kk + tig]);
                af[mi][1] = __float_as_uint(pA[(m + 8) * 20 + kk + tig]);
                af[mi][2] = __float_as_uint(pA[m * 20 + kk + tig + 4]);
                af[mi][3] = __float_as_uint(pA[(m + 8) * 20 + kk + tig + 4]);
            }
#pragma unroll
            for (int nj = 0; nj < 4; nj++) {
                int n = wn * 32 + nj * 8 + grp;
                bf[nj][0] = __float_as_uint(pB[(kk + tig) * 136 + n]);
                bf[nj][1] = __float_as_uint(pB[(kk + tig + 4) * 136 + n]);
            }
#pragma unroll
            for (int mi = 0; mi < 4; mi++)
#pragma unroll
                for (int nj = 0; nj < 4; nj++)
                    MMA_TF32(acc[mi][nj], af[mi], bf[nj]);
        }
    }
#undef G_LOAD

#pragma unroll
    for (int mi = 0; mi < 4; mi++) {
        int r0 = m0 + wm * 64 + mi * 16 + grp;
#pragma unroll
        for (int nj = 0; nj < 4; nj++) {
            int c0 = n0 + wn * 32 + nj * 8 + tig * 2;
            scatter(mode, r0,     c0,     acc[mi][nj][0] + bias[c0],     out);
            scatter(mode, r0,     c0 + 1, acc[mi][nj][1] + bias[c0 + 1], out);
            scatter(mode, r0 + 8, c0,     acc[mi][nj][2] + bias[c0],     out);
            scatter(mode, r0 + 8, c0 + 1, acc[mi][nj][3] + bias[c0 + 1], out);
        }
    }
}

// =============================================================================
// Fused attention: block = (head-batch, 64 q rows), 512 threads, 16 warps.
// Chunk skipping with warp-parallel analysis; ALL needed K chunks prefetched
// upfront into 4 smem buffers (163KB dyn smem).
// =============================================================================
#define OFF_Q     0                    // [q][kpacked] stride 68, 64x68
#define OFF_K     4352                 // 4 bufs of [k][n] stride 136 (8704 w each)
#define OFF_P     4352                 // phase2 overlay: [q][kpacked] stride 140
#define OFF_V     13312                // phase2 overlay: [s][d] stride 72, 128x72
#define OFF_MODS  39168
#define OFF_RED   39680                // 16 x 64
#define OFF_RMAX  40704
#define OFF_RINV  40768
#define OFF_CMSK  40832                // 4: per-chunk modality bitmask
#define OFF_RSUM  40836                // 2: row modality mask, row-has-latent
#define OFF_LIST  40840                // 4: needed chunk ids
#define OFF_NCH   40844
#define ATTN_SMEM_WORDS 40848
#define ATTN_SMEM_BYTES (ATTN_SMEM_WORDS * 4)   // 163392

__device__ __forceinline__ int modbit(int m) {
    return (m == -1) ? 4 : (m == 0) ? 1 : (m == 1) ? 2 : 8;
}

__global__ __launch_bounds__(512, 1) void attn_fused(
    const int* __restrict__ mods, const int* __restrict__ nlp)
{
    unsigned* sQ     = dsm + OFF_Q;
    float*    sK     = (float*)(dsm + OFF_K);
    unsigned* sP     = dsm + OFF_P;
    float*    sV     = (float*)(dsm + OFF_V);
    int*      s_mods = (int*)(dsm + OFF_MODS);
    float*    s_red  = (float*)(dsm + OFF_RED);
    float*    s_rmax = (float*)(dsm + OFF_RMAX);
    float*    s_rinv = (float*)(dsm + OFF_RINV);
    int*      s_cmsk = (int*)(dsm + OFF_CMSK);
    int*      s_rsum = (int*)(dsm + OFF_RSUM);
    int*      s_list = (int*)(dsm + OFF_LIST);
    int*      s_nch  = (int*)(dsm + OFF_NCH);

    const int tid  = threadIdx.x;
    const int lane = tid & 31, w = tid >> 5;
    const int grp  = lane >> 2, tig = lane & 3;
    const int wm = w & 1, wn = w >> 1;          // 2 x 8 warp grid
    const int batch = blockIdx.y;
    const int m0 = blockIdx.x * 64;
    const int bt = batch / NHEAD, h = batch % NHEAD;
    const int nlat = nlp ? *nlp : 32;

    const float* __restrict__ Qp = g_Q  + (size_t)batch * SEQ * HDIM;
    const float* __restrict__ Kp = g_Kt + (size_t)batch * HDIM * SEQ;
    const float* __restrict__ Vp = g_V  + (size_t)batch * SEQ * HDIM;
    const unsigned smem_u32 = (unsigned)__cvta_generic_to_shared(dsm);

    int my_mod = mods[tid];
    s_mods[tid] = my_mod;
    if (tid < 8) ((int*)(dsm + OFF_CMSK))[tid] = 0;   // zero cmsk/rsum/list area
    {   // Q tile, packed-pair layout (values already tf32-rounded)
        int q = tid >> 3, j = tid & 7;
        const float* src = Qp + (size_t)(m0 + q) * HDIM + j * 8;
        float4 a = *(const float4*)src;
        float4 b = *(const float4*)(src + 4);
        unsigned* dst = sQ + q * 68 + j * 8;
        dst[0] = __float_as_uint(a.x); dst[1] = __float_as_uint(b.x);
        dst[2] = __float_as_uint(a.y); dst[3] = __float_as_uint(b.y);
        dst[4] = __float_as_uint(a.z); dst[5] = __float_as_uint(b.z);
        dst[6] = __float_as_uint(a.w); dst[7] = __float_as_uint(b.w);
    }
    __syncthreads();

    // ---------------- chunk analysis (warp-parallel) ----------------
    {
        int mb = modbit(my_mod);                // key-side bit for key tid
#pragma unroll
        for (int d = 16; d >= 1; d >>= 1)
            mb |= __shfl_xor_sync(0xffffffffu, mb, d);
        if (lane == 0) atomicOr(&s_cmsk[w >> 2], mb);   // 4 warps per 128-key chunk
        if (tid < 64) {
            int rg = m0 + tid;
            int rb = (rg < nlat) ? 0 : modbit(s_mods[rg]);
            int rl = (rg < nlat) ? 1 : 0;
#pragma unroll
            for (int d = 16; d >= 1; d >>= 1) {
                rb |= __shfl_xor_sync(0xffffffffu, rb, d);
                rl |= __shfl_xor_sync(0xffffffffu, rl, d);
            }
            if (lane == 0) { atomicOr(&s_rsum[0], rb); atomicOr(&s_rsum[1], rl); }
        }
    }
    __syncthreads();
    if (tid == 0) {
        int n = 0;
        for (int c = 0; c < 4; c++)
            if (s_rsum[1] || (s_rsum[0] & s_cmsk[c])) s_list[n++] = c;
        *s_nch = n;
    }
    __syncthreads();
    const int nch = *s_nch;

    // issue ALL needed K-chunk loads upfront (one commit group per chunk)
#define LOAD_K(buf, c)                                                            \
    {                                                                             \
        _Pragma("unroll")                                                         \
        for (int rep = 0; rep < 4; rep++) {                                       \
            int idx = rep * 512 + tid;                                            \
            int r = idx >> 5, c4 = (idx & 31) * 4;                                \
            cp16(smem_u32 + (unsigned)((OFF_K + (buf) * 8704 + r * 136 + c4) * 4),\
                 Kp + (size_t)r * SEQ + (c) * 128 + c4);                          \
        }                                                                         \
        asm volatile("cp.async.commit_group;" ::: "memory");                      \
    }
    for (int j = 0; j < nch; j++) LOAD_K(j, s_list[j]);
#undef LOAD_K

    float S[4][2][2][4];
#pragma unroll
    for (int c = 0; c < 4; c++)
#pragma unroll
        for (int i = 0; i < 2; i++)
#pragma unroll
            for (int j = 0; j < 2; j++)
#pragma unroll
                for (int e = 0; e < 4; e++) S[c][i][j][e] = 0.0f;

    const unsigned* qr0 = sQ + (wm * 32 + grp) * 68 + 2 * tig;
    const unsigned* qr1 = sQ + (wm * 32 + grp + 8) * 68 + 2 * tig;
    const unsigned* qr2 = sQ + (wm * 32 + grp + 16) * 68 + 2 * tig;
    const unsigned* qr3 = sQ + (wm * 32 + grp + 24) * 68 + 2 * tig;
    const int bn0 = wn * 16 + grp;

    // ---------------- phase 1: S = Q @ K^T (needed chunks only) -------------
#pragma unroll
    for (int j = 0; j < 4; j++) {
        if (j >= nch) break;
        wait_pending(nch - 1 - j);
        __syncthreads();
        const float* pK = sK + j * 8704;
#pragma unroll
        for (int kk = 0; kk < 64; kk += 8) {
            uint2 u00 = *(const uint2*)(qr0 + kk);
            uint2 u01 = *(const uint2*)(qr1 + kk);
            uint2 u10 = *(const uint2*)(qr2 + kk);
            uint2 u11 = *(const uint2*)(qr3 + kk);
            unsigned af0[4] = {u00.x, u01.x, u00.y, u01.y};
            unsigned af1[4] = {u10.x, u11.x, u10.y, u11.y};
            unsigned bf0[2] = { __float_as_uint(pK[(kk + tig) * 136 + bn0]),
                                __float_as_uint(pK[(kk + tig + 4) * 136 + bn0]) };
            unsigned bf1[2] = { __float_as_uint(pK[(kk + tig) * 136 + bn0 + 8]),
                                __float_as_uint(pK[(kk + tig + 4) * 136 + bn0 + 8]) };
            MMA_TF32(S[j][0][0], af0, bf0);
            MMA_TF32(S[j][0][1], af0, bf1);
            MMA_TF32(S[j][1][0], af1, bf0);
            MMA_TF32(S[j][1][1], af1, bf1);
        }
    }

    // ---------------- mask + softmax (needed chunks only) -------------------
    int rloc[4]; int mq[4]; bool lat[4]; float lm[4];
#pragma unroll
    for (int rr = 0; rr < 4; rr++) {
        int mi = rr >> 1, hh = rr & 1;
        rloc[rr] = wm * 32 + mi * 16 + hh * 8 + grp;
        int rg = m0 + rloc[rr];
        lat[rr] = (rg < nlat);
        mq[rr] = s_mods[rg];
        lm[rr] = -3.0e38f;
    }
#pragma unroll
    for (int j = 0; j < 4; j++) {
        if (j >= nch) break;
        int c = s_list[j];
#pragma unroll
        for (int nj = 0; nj < 2; nj++) {
            int k0 = c * 128 + wn * 16 + nj * 8 + 2 * tig;
            int md0 = s_mods[k0], md1 = s_mods[k0 + 1];
#pragma unroll
            for (int rr = 0; rr < 4; rr++) {
                int mi = rr >> 1, hh = rr & 1;
                float& s0 = S[j][mi][nj][hh * 2 + 0];
                float& s1 = S[j][mi][nj][hh * 2 + 1];
                if (!(lat[rr] || mq[rr] == md0)) s0 = -3.0e38f;
                if (!(lat[rr] || mq[rr] == md1)) s1 = -3.0e38f;
                lm[rr] = fmaxf(lm[rr], fmaxf(s0, s1));
            }
        }
    }
#pragma unroll
    for (int rr = 0; rr < 4; rr++) {
        lm[rr] = fmaxf(lm[rr], __shfl_xor_sync(0xffffffffu, lm[rr], 1));
        lm[rr] = fmaxf(lm[rr], __shfl_xor_sync(0xffffffffu, lm[rr], 2));
    }
    if (tig == 0) {
#pragma unroll
        for (int rr = 0; rr < 4; rr++) s_red[w * 64 + rloc[rr]] = lm[rr];
    }
    __syncthreads();
    if (tid < 64) {
        int wsel = tid >> 5;
        float m = -3.0e38f;
#pragma unroll
        for (int j = 0; j < 8; j++) m = fmaxf(m, s_red[(2 * j + wsel) * 64 + tid]);
        s_rmax[tid] = m;
    }
    __syncthreads();

    float rm[4], ls[4];
#pragma unroll
    for (int rr = 0; rr < 4; rr++) { rm[rr] = s_rmax[rloc[rr]]; ls[rr] = 0.0f; }
#pragma unroll
    for (int j = 0; j < 4; j++) {
        if (j >= nch) break;
#pragma unroll
        for (int nj = 0; nj < 2; nj++)
#pragma unroll
            for (int rr = 0; rr < 4; rr++) {
                int mi = rr >> 1, hh = rr & 1;
                float& s0 = S[j][mi][nj][hh * 2 + 0];
                float& s1 = S[j][mi][nj][hh * 2 + 1];
                s0 = __expf(s0 - rm[rr]);
                s1 = __expf(s1 - rm[rr]);
                ls[rr] += s0 + s1;
            }
    }
#pragma unroll
    for (int rr = 0; rr < 4; rr++) {
        ls[rr] += __shfl_xor_sync(0xffffffffu, ls[rr], 1);
        ls[rr] += __shfl_xor_sync(0xffffffffu, ls[rr], 2);
    }
    if (tig == 0) {
#pragma unroll
        for (int rr = 0; rr < 4; rr++) s_red[w * 64 + rloc[rr]] = ls[rr];
    }
    __syncthreads();
    if (tid < 64) {
        int wsel = tid >> 5;
        float s = 0.0f;
#pragma unroll
        for (int j = 0; j < 8; j++) s += s_red[(2 * j + wsel) * 64 + tid];
        s_rinv[tid] = 1.0f / s;
    }

    // ---------------- phase 2: O = P @ V (needed chunks only) ---------------
    float O0[4] = {0.0f, 0.0f, 0.0f, 0.0f};
    float O1[4] = {0.0f, 0.0f, 0.0f, 0.0f};
    const int vn = wn * 8 + grp;
    const unsigned* pr0 = sP + (wm * 32 + grp) * 140 + 2 * tig;
    const unsigned* pr1 = sP + (wm * 32 + grp + 8) * 140 + 2 * tig;
    const unsigned* pr2 = sP + (wm * 32 + grp + 16) * 140 + 2 * tig;
    const unsigned* pr3 = sP + (wm * 32 + grp + 24) * 140 + 2 * tig;

#pragma unroll
    for (int j = 0; j < 4; j++) {
        if (j >= nch) break;
        int c = s_list[j];
        __syncthreads();
#pragma unroll
        for (int rep = 0; rep < 4; rep++) {
            int idx = rep * 512 + tid;
            int r = idx >> 4, d4 = (idx & 15) * 4;
            cp16(smem_u32 + (unsigned)((OFF_V + r * 72 + d4) * 4),
                 Vp + (size_t)(c * 128 + r) * HDIM + d4);
        }
        asm volatile("cp.async.commit_group;" ::: "memory");
#pragma unroll
        for (int nj = 0; nj < 2; nj++)
#pragma unroll
            for (int b = 0; b < 2; b++) {
                int kl = wn * 16 + nj * 8 + 2 * tig + b;
                int pos = (kl >> 3) * 8 + (kl & 3) * 2 + ((kl >> 2) & 1);
#pragma unroll
                for (int rr = 0; rr < 4; rr++) {
                    int mi = rr >> 1, hh = rr & 1;
                    sP[rloc[rr] * 140 + pos] = f2tf(S[j][mi][nj][hh * 2 + b]);
                }
            }
        asm volatile("cp.async.wait_group 0;" ::: "memory");
        __syncthreads();
#pragma unroll
        for (int kk = 0; kk < 128; kk += 8) {
            uint2 u00 = *(const uint2*)(pr0 + kk);
            uint2 u01 = *(const uint2*)(pr1 + kk);
            uint2 u10 = *(const uint2*)(pr2 + kk);
            uint2 u11 = *(const uint2*)(pr3 + kk);
            unsigned af0[4] = {u00.x, u01.x, u00.y, u01.y};
            unsigned af1[4] = {u10.x, u11.x, u10.y, u11.y};
            unsigned bf[2] = { __float_as_uint(sV[(kk + tig) * 72 + vn]),
                               __float_as_uint(sV[(kk + tig + 4) * 72 + vn]) };
            MMA_TF32(O0, af0, bf);
            MMA_TF32(O1, af1, bf);
        }
    }

    // epilogue: normalize, tf32-round, write ctx
#pragma unroll
    for (int rr = 0; rr < 4; rr++) {
        int mi = rr >> 1, hh = rr & 1;
        const float* Osel = mi ? O1 : O0;
        float inv = s_rinv[rloc[rr]];
        float2 val;
        val.x = f2tff(Osel[hh * 2 + 0] * inv);
        val.y = f2tff(Osel[hh * 2 + 1] * inv);
        int d0 = wn * 8 + 2 * tig;
        *(float2*)(g_CTX + (size_t)(bt * SEQ + m0 + rloc[rr]) * DMODEL
                   + h * HDIM + d0) = val;
    }
}

// =============================================================================
extern "C" void kernel_launch(void* const* d_in, const int* in_sizes, int n_in,
                              void* d_out, int out_size)
{
    const float* x  = (const float*)d_in[0];
    const float* Wq = (const float*)d_in[1];
    const float* bq = (const float*)d_in[2];
    const float* Wk = (const float*)d_in[3];
    const float* bk = (const float*)d_in[4];
    const float* Wv = (const float*)d_in[5];
    const float* bv = (const float*)d_in[6];
    const float* Wo = (const float*)d_in[7];
    const float* bo = (const float*)d_in[8];
    const int* mods = (const int*)d_in[9];
    const int* nlp  = (n_in > 10) ? (const int*)d_in[10] : nullptr;
    float* out = (float*)d_out;

    cudaFuncSetAttribute(gemm768, cudaFuncAttributeMaxDynamicSharedMemorySize,
                         GD_BYTES);
    cudaFuncSetAttribute(attn_fused, cudaFuncAttributeMaxDynamicSharedMemorySize,
                         ATTN_SMEM_BYTES);

    prep_round<<<(PREP_QUADS + 255) / 256, 256>>>(x, Wq, Wk, Wv, Wo);
    gemm768<<<dim3(6, 128, 3), 256, GD_BYTES>>>(bq, bk, bv, bo, nullptr, 0);
    attn_fused<<<dim3(SEQ / 64, NBATCH), 512, ATTN_SMEM_BYTES>>>(mods, nlp);
    gemm768<<<dim3(6, 128, 1), 256, GD_BYTES>>>(bq, bk, bv, bo, out, 3);
}

// round 14
// speedup vs baseline: 1.2223x; 1.0133x over previous
#include <cuda_runtime.h>
#include <math.h>

// Problem constants
#define MROWS  16384   // B*T*S = 32*512
#define DMODEL 768
#define SEQ    512
#define NHEAD  12
#define HDIM   64
#define NBATCH 384     // (B*T)*H = 32*12

// ---------------- scratch (static device memory; no allocation) --------------
__device__ float g_Q  [(size_t)NBATCH * SEQ * HDIM];   // [b*h][s][d] (pre-scaled, tf32-rounded)
__device__ float g_Kt [(size_t)NBATCH * HDIM * SEQ];   // [b*h][d][s] (tf32-rounded)
__device__ float g_V  [(size_t)NBATCH * SEQ * HDIM];   // [b*h][s][d] (tf32-rounded)
__device__ float g_CTX[(size_t)MROWS * DMODEL];        // [row][h*64+d] (tf32-rounded)

// ---------------- helpers ----------------
__device__ __forceinline__ unsigned f2tf(float f) {
    unsigned u;
    asm("cvt.rna.tf32.f32 %0, %1;" : "=r"(u) : "f"(f));
    return u;
}
__device__ __forceinline__ float f2tff(float f) { return __uint_as_float(f2tf(f)); }

__device__ __forceinline__ void cp16(unsigned dst, const void* src) {
    asm volatile("cp.async.ca.shared.global [%0], [%1], 16;" :: "r"(dst), "l"(src));
}
__device__ __forceinline__ void wait_pending(int n) {
    if (n <= 0)      asm volatile("cp.async.wait_group 0;" ::: "memory");
    else if (n == 1) asm volatile("cp.async.wait_group 1;" ::: "memory");
    else if (n == 2) asm volatile("cp.async.wait_group 2;" ::: "memory");
    else             asm volatile("cp.async.wait_group 3;" ::: "memory");
}

#define MMA_TF32(d, a, b)                                                          \
    asm volatile(                                                                  \
        "mma.sync.aligned.m16n8k8.row.col.f32.tf32.tf32.f32 "                      \
        "{%0,%1,%2,%3}, {%4,%5,%6,%7}, {%8,%9}, {%0,%1,%2,%3};"                    \
        : "+f"((d)[0]), "+f"((d)[1]), "+f"((d)[2]), "+f"((d)[3])                   \
        : "r"((a)[0]), "r"((a)[1]), "r"((a)[2]), "r"((a)[3]),                      \
          "r"((b)[0]), "r"((b)[1]))

// scatter for projection GEMM epilogues (rounds for modes 0-2)
__device__ __forceinline__ void scatter(int mode, int m, int n, float v,
                                        float* __restrict__ out) {
    int bt = m >> 9, s = m & 511;
    int h = n >> 6, d = n & 63;
    if (mode == 0) {
        g_Q[((size_t)(bt * NHEAD + h) * SEQ + s) * HDIM + d] = f2tff(v * 0.125f);
    } else if (mode == 1) {
        g_Kt[((size_t)(bt * NHEAD + h) * HDIM + d) * SEQ + s] = f2tff(v);
    } else if (mode == 2) {
        g_V[((size_t)(bt * NHEAD + h) * SEQ + s) * HDIM + d] = f2tff(v);
    } else {
        out[(size_t)m * DMODEL + n] = v;
    }
}

extern __shared__ unsigned dsm[];

// =============================================================================
// 128x128 tf32-MMA GEMM over K=768. v4: 128 threads = 4 warps, warp grid 2x2,
// warp tile 64x64 (best measured shape), 4-stage cp.async pipeline, cvt at
// fragment load (reads raw x/W directly — no prep pass). QKV via gridDim.z.
// stage layout (words): A [m][k] stride 20 (2560 w), B [k][n] stride 136 (2176 w)
// =============================================================================
#define GST_WORDS 4736
#define GD_BYTES  (4 * GST_WORDS * 4)   // 75776

__global__ __launch_bounds__(128, 2) void gemm768(
    const float* __restrict__ x,
    const float* __restrict__ Wq, const float* __restrict__ Wk,
    const float* __restrict__ Wv, const float* __restrict__ Wo,
    const float* __restrict__ bq, const float* __restrict__ bk,
    const float* __restrict__ bv, const float* __restrict__ bo,
    float* __restrict__ out, int base_mode)
{
    float* sm = (float*)dsm;
    const int mode = base_mode + blockIdx.z;
    const float* __restrict__ bias =
        (mode == 0) ? bq : (mode == 1) ? bk : (mode == 2) ? bv : bo;
    const float* __restrict__ A = (mode == 3) ? (const float*)g_CTX : x;
    const float* __restrict__ W =
        (mode == 0) ? Wq : (mode == 1) ? Wk : (mode == 2) ? Wv : Wo;

    const int tid  = threadIdx.x;
    const int lane = tid & 31, warp = tid >> 5;
    const int wm = warp & 1, wn = warp >> 1;     // 2 x 2 warp grid
    const int grp = lane >> 2, tig = lane & 3;
    const int m0 = blockIdx.y * 128;
    const int n0 = blockIdx.x * 128;

    const unsigned s_u32 = (unsigned)__cvta_generic_to_shared(dsm);

    float acc[4][8][4];
#pragma unroll
    for (int i = 0; i < 4; i++)
#pragma unroll
        for (int j = 0; j < 8; j++)
#pragma unroll
            for (int e = 0; e < 4; e++) acc[i][j][e] = 0.0f;

#define G_LOAD(st, k0)                                                            \
    {                                                                             \
        _Pragma("unroll")                                                         \
        for (int rep = 0; rep < 4; rep++) {                                       \
            int t = rep * 128 + tid;                                              \
            int r = t >> 2, c4 = (t & 3) * 4;                                     \
            cp16(s_u32 + (unsigned)(((st) * GST_WORDS + r * 20 + c4) * 4),        \
                 A + (size_t)(m0 + r) * DMODEL + (k0) + c4);                      \
        }                                                                         \
        _Pragma("unroll")                                                         \
        for (int rep = 0; rep < 4; rep++) {                                       \
            int t = rep * 128 + tid;                                              \
            int r = t >> 5, c4 = (t & 31) * 4;                                    \
            cp16(s_u32 + (unsigned)(((st) * GST_WORDS + 2560 + r * 136 + c4) * 4),\
                 W + (size_t)((k0) + r) * DMODEL + n0 + c4);                      \
        }                                                                         \
        asm volatile("cp.async.commit_group;" ::: "memory");                      \
    }

    G_LOAD(0, 0);
    G_LOAD(1, 16);
    G_LOAD(2, 32);

    for (int ci = 0; ci < 48; ci++) {
        asm volatile("cp.async.wait_group 2;" ::: "memory");
        __syncthreads();
        if (ci + 3 < 48) G_LOAD((ci + 3) & 3, (ci + 3) * 16);

        const float* pA = sm + (ci & 3) * GST_WORDS;
        const float* pB = pA + 2560;
#pragma unroll
        for (int kk = 0; kk < 16; kk += 8) {
            unsigned af[4][4], bf[8][2];
#pragma unroll
            for (int mi = 0; mi < 4; mi++) {
                int m = wm * 64 + mi * 16 + grp;
                af[mi][0] = f2tf(pA[m * 20 + kk + tig]);
                af[mi][1] = f2tf(pA[(m + 8) * 20 + kk + tig]);
                af[mi][2] = f2tf(pA[m * 20 + kk + tig + 4]);
                af[mi][3] = f2tf(pA[(m + 8) * 20 + kk + tig + 4]);
            }
#pragma unroll
            for (int nj = 0; nj < 8; nj++) {
                int n = wn * 64 + nj * 8 + grp;
                bf[nj][0] = f2tf(pB[(kk + tig) * 136 + n]);
                bf[nj][1] = f2tf(pB[(kk + tig + 4) * 136 + n]);
            }
#pragma unroll
            for (int mi = 0; mi < 4; mi++)
#pragma unroll
                for (int nj = 0; nj < 8; nj++)
                    MMA_TF32(acc[mi][nj], af[mi], bf[nj]);
        }
    }
#undef G_LOAD

#pragma unroll
    for (int mi = 0; mi < 4; mi++) {
        int r0 = m0 + wm * 64 + mi * 16 + grp;
#pragma unroll
        for (int nj = 0; nj < 8; nj++) {
            int c0 = n0 + wn * 64 + nj * 8 + tig * 2;
            scatter(mode, r0,     c0,     acc[mi][nj][0] + bias[c0],     out);
            scatter(mode, r0,     c0 + 1, acc[mi][nj][1] + bias[c0 + 1], out);
            scatter(mode, r0 + 8, c0,     acc[mi][nj][2] + bias[c0],     out);
            scatter(mode, r0 + 8, c0 + 1, acc[mi][nj][3] + bias[c0 + 1], out);
        }
    }
}

// =============================================================================
// Fused attention: block = (head-batch, 64 q rows), 512 threads, 16 warps.
// Chunk skipping, all-K upfront prefetch, NEW: double-buffered V prefetch
// (V chunk 0 issued during softmax; chunk j+1 issued before chunk j's MMAs).
// =============================================================================
#define OFF_Q     0                    // [q][kpacked] stride 68, 64x68
#define OFF_K     4352                 // 4 bufs of [k][n] stride 136 (8704 w each)
#define OFF_P     4352                 // phase2 overlay: [q][kpacked] stride 140
#define OFF_V     13312                // phase2 overlay: 2 bufs [s][d] stride 72 (9216 w)
#define OFF_MODS  39168
#define OFF_RED   39680                // 16 x 64
#define OFF_RMAX  40704
#define OFF_RINV  40768
#define OFF_CMSK  40832                // 4: per-chunk modality bitmask
#define OFF_RSUM  40836                // 2: row modality mask, row-has-latent
#define OFF_LIST  40840                // 4: needed chunk ids
#define OFF_NCH   40844
#define ATTN_SMEM_WORDS 40848
#define ATTN_SMEM_BYTES (ATTN_SMEM_WORDS * 4)   // 163392

__device__ __forceinline__ int modbit(int m) {
    return (m == -1) ? 4 : (m == 0) ? 1 : (m == 1) ? 2 : 8;
}

__global__ __launch_bounds__(512, 1) void attn_fused(
    const int* __restrict__ mods, const int* __restrict__ nlp)
{
    unsigned* sQ     = dsm + OFF_Q;
    float*    sK     = (float*)(dsm + OFF_K);
    unsigned* sP     = dsm + OFF_P;
    float*    sV     = (float*)(dsm + OFF_V);
    int*      s_mods = (int*)(dsm + OFF_MODS);
    float*    s_red  = (float*)(dsm + OFF_RED);
    float*    s_rmax = (float*)(dsm + OFF_RMAX);
    float*    s_rinv = (float*)(dsm + OFF_RINV);
    int*      s_cmsk = (int*)(dsm + OFF_CMSK);
    int*      s_rsum = (int*)(dsm + OFF_RSUM);
    int*      s_list = (int*)(dsm + OFF_LIST);
    int*      s_nch  = (int*)(dsm + OFF_NCH);

    const int tid  = threadIdx.x;
    const int lane = tid & 31, w = tid >> 5;
    const int grp  = lane >> 2, tig = lane & 3;
    const int wm = w & 1, wn = w >> 1;          // 2 x 8 warp grid
    const int batch = blockIdx.y;
    const int m0 = blockIdx.x * 64;
    const int bt = batch / NHEAD, h = batch % NHEAD;
    const int nlat = nlp ? *nlp : 32;

    const float* __restrict__ Qp = g_Q  + (size_t)batch * SEQ * HDIM;
    const float* __restrict__ Kp = g_Kt + (size_t)batch * HDIM * SEQ;
    const float* __restrict__ Vp = g_V  + (size_t)batch * SEQ * HDIM;
    const unsigned smem_u32 = (unsigned)__cvta_generic_to_shared(dsm);

    int my_mod = mods[tid];
    s_mods[tid] = my_mod;
    if (tid < 8) ((int*)(dsm + OFF_CMSK))[tid] = 0;
    {   // Q tile, packed-pair layout (values already tf32-rounded)
        int q = tid >> 3, j = tid & 7;
        const float* src = Qp + (size_t)(m0 + q) * HDIM + j * 8;
        float4 a = *(const float4*)src;
        float4 b = *(const float4*)(src + 4);
        unsigned* dst = sQ + q * 68 + j * 8;
        dst[0] = __float_as_uint(a.x); dst[1] = __float_as_uint(b.x);
        dst[2] = __float_as_uint(a.y); dst[3] = __float_as_uint(b.y);
        dst[4] = __float_as_uint(a.z); dst[5] = __float_as_uint(b.z);
        dst[6] = __float_as_uint(a.w); dst[7] = __float_as_uint(b.w);
    }
    __syncthreads();

    // ---------------- chunk analysis (warp-parallel) ----------------
    {
        int mb = modbit(my_mod);
#pragma unroll
        for (int d = 16; d >= 1; d >>= 1)
            mb |= __shfl_xor_sync(0xffffffffu, mb, d);
        if (lane == 0) atomicOr(&s_cmsk[w >> 2], mb);
        if (tid < 64) {
            int rg = m0 + tid;
            int rb = (rg < nlat) ? 0 : modbit(s_mods[rg]);
            int rl = (rg < nlat) ? 1 : 0;
#pragma unroll
            for (int d = 16; d >= 1; d >>= 1) {
                rb |= __shfl_xor_sync(0xffffffffu, rb, d);
                rl |= __shfl_xor_sync(0xffffffffu, rl, d);
            }
            if (lane == 0) { atomicOr(&s_rsum[0], rb); atomicOr(&s_rsum[1], rl); }
        }
    }
    __syncthreads();
    if (tid == 0) {
        int n = 0;
        for (int c = 0; c < 4; c++)
            if (s_rsum[1] || (s_rsum[0] & s_cmsk[c])) s_list[n++] = c;
        *s_nch = n;
    }
    __syncthreads();
    const int nch = *s_nch;

    // issue ALL needed K-chunk loads upfront (one commit group per chunk)
#define LOAD_K(buf, c)                                                            \
    {                                                                             \
        _Pragma("unroll")                                                         \
        for (int rep = 0; rep < 4; rep++) {                                       \
            int idx = rep * 512 + tid;                                            \
            int r = idx >> 5, c4 = (idx & 31) * 4;                                \
            cp16(smem_u32 + (unsigned)((OFF_K + (buf) * 8704 + r * 136 + c4) * 4),\
                 Kp + (size_t)r * SEQ + (c) * 128 + c4);                          \
        }                                                                         \
        asm volatile("cp.async.commit_group;" ::: "memory");                      \
    }
#define LOAD_V(buf, c)                                                            \
    {                                                                             \
        _Pragma("unroll")                                                         \
        for (int rep = 0; rep < 4; rep++) {                                       \
            int idx = rep * 512 + tid;                                            \
            int r = idx >> 4, d4 = (idx & 15) * 4;                                \
            cp16(smem_u32 + (unsigned)((OFF_V + (buf) * 9216 + r * 72 + d4) * 4), \
                 Vp + (size_t)((c) * 128 + r) * HDIM + d4);                       \
        }                                                                         \
        asm volatile("cp.async.commit_group;" ::: "memory");                      \
    }
    for (int j = 0; j < nch; j++) LOAD_K(j, s_list[j]);

    float S[4][2][2][4];
#pragma unroll
    for (int c = 0; c < 4; c++)
#pragma unroll
        for (int i = 0; i < 2; i++)
#pragma unroll
            for (int j = 0; j < 2; j++)
#pragma unroll
                for (int e = 0; e < 4; e++) S[c][i][j][e] = 0.0f;

    const unsigned* qr0 = sQ + (wm * 32 + grp) * 68 + 2 * tig;
    const unsigned* qr1 = sQ + (wm * 32 + grp + 8) * 68 + 2 * tig;
    const unsigned* qr2 = sQ + (wm * 32 + grp + 16) * 68 + 2 * tig;
    const unsigned* qr3 = sQ + (wm * 32 + grp + 24) * 68 + 2 * tig;
    const int bn0 = wn * 16 + grp;

    // ---------------- phase 1: S = Q @ K^T (needed chunks only) -------------
#pragma unroll
    for (int j = 0; j < 4; j++) {
        if (j >= nch) break;
        wait_pending(nch - 1 - j);
        __syncthreads();
        const float* pK = sK + j * 8704;
#pragma unroll
        for (int kk = 0; kk < 64; kk += 8) {
            uint2 u00 = *(const uint2*)(qr0 + kk);
            uint2 u01 = *(const uint2*)(qr1 + kk);
            uint2 u10 = *(const uint2*)(qr2 + kk);
            uint2 u11 = *(const uint2*)(qr3 + kk);
            unsigned af0[4] = {u00.x, u01.x, u00.y, u01.y};
            unsigned af1[4] = {u10.x, u11.x, u10.y, u11.y};
            unsigned bf0[2] = { __float_as_uint(pK[(kk + tig) * 136 + bn0]),
                                __float_as_uint(pK[(kk + tig + 4) * 136 + bn0]) };
            unsigned bf1[2] = { __float_as_uint(pK[(kk + tig) * 136 + bn0 + 8]),
                                __float_as_uint(pK[(kk + tig + 4) * 136 + bn0 + 8]) };
            MMA_TF32(S[j][0][0], af0, bf0);
            MMA_TF32(S[j][0][1], af0, bf1);
            MMA_TF32(S[j][1][0], af1, bf0);
            MMA_TF32(S[j][1][1], af1, bf1);
        }
    }

    // ---------------- mask + softmax (needed chunks only) -------------------
    int rloc[4]; int mq[4]; bool lat[4]; float lm[4];
#pragma unroll
    for (int rr = 0; rr < 4; rr++) {
        int mi = rr >> 1, hh = rr & 1;
        rloc[rr] = wm * 32 + mi * 16 + hh * 8 + grp;
        int rg = m0 + rloc[rr];
        lat[rr] = (rg < nlat);
        mq[rr] = s_mods[rg];
        lm[rr] = -3.0e38f;
    }
#pragma unroll
    for (int j = 0; j < 4; j++) {
        if (j >= nch) break;
        int c = s_list[j];
#pragma unroll
        for (int nj = 0; nj < 2; nj++) {
            int k0 = c * 128 + wn * 16 + nj * 8 + 2 * tig;
            int md0 = s_mods[k0], md1 = s_mods[k0 + 1];
#pragma unroll
            for (int rr = 0; rr < 4; rr++) {
                int mi = rr >> 1, hh = rr & 1;
                float& s0 = S[j][mi][nj][hh * 2 + 0];
                float& s1 = S[j][mi][nj][hh * 2 + 1];
                if (!(lat[rr] || mq[rr] == md0)) s0 = -3.0e38f;
                if (!(lat[rr] || mq[rr] == md1)) s1 = -3.0e38f;
                lm[rr] = fmaxf(lm[rr], fmaxf(s0, s1));
            }
        }
    }
#pragma unroll
    for (int rr = 0; rr < 4; rr++) {
        lm[rr] = fmaxf(lm[rr], __shfl_xor_sync(0xffffffffu, lm[rr], 1));
        lm[rr] = fmaxf(lm[rr], __shfl_xor_sync(0xffffffffu, lm[rr], 2));
    }
    if (tig == 0) {
#pragma unroll
        for (int rr = 0; rr < 4; rr++) s_red[w * 64 + rloc[rr]] = lm[rr];
    }
    __syncthreads();

    // prefetch first V chunk (K buffers fully consumed; overlaps softmax)
    LOAD_V(0, s_list[0]);

    if (tid < 64) {
        int wsel = tid >> 5;
        float m = -3.0e38f;
#pragma unroll
        for (int j = 0; j < 8; j++) m = fmaxf(m, s_red[(2 * j + wsel) * 64 + tid]);
        s_rmax[tid] = m;
    }
    __syncthreads();

    float rm[4], ls[4];
#pragma unroll
    for (int rr = 0; rr < 4; rr++) { rm[rr] = s_rmax[rloc[rr]]; ls[rr] = 0.0f; }
#pragma unroll
    for (int j = 0; j < 4; j++) {
        if (j >= nch) break;
#pragma unroll
        for (int nj = 0; nj < 2; nj++)
#pragma unroll
            for (int rr = 0; rr < 4; rr++) {
                int mi = rr >> 1, hh = rr & 1;
                float& s0 = S[j][mi][nj][hh * 2 + 0];
                float& s1 = S[j][mi][nj][hh * 2 + 1];
                s0 = __expf(s0 - rm[rr]);
                s1 = __expf(s1 - rm[rr]);
                ls[rr] += s0 + s1;
            }
    }
#pragma unroll
    for (int rr = 0; rr < 4; rr++) {
        ls[rr] += __shfl_xor_sync(0xffffffffu, ls[rr], 1);
        ls[rr] += __shfl_xor_sync(0xffffffffu, ls[rr], 2);
    }
    if (tig == 0) {
#pragma unroll
        for (int rr = 0; rr < 4; rr++) s_red[w * 64 + rloc[rr]] = ls[rr];
    }
    __syncthreads();
    if (tid < 64) {
        int wsel = tid >> 5;
        float s = 0.0f;
#pragma unroll
        for (int j = 0; j < 8; j++) s += s_red[(2 * j + wsel) * 64 + tid];
        s_rinv[tid] = 1.0f / s;
    }

    // ---------------- phase 2: O = P @ V (double-buffered V) ---------------
    float O0[4] = {0.0f, 0.0f, 0.0f, 0.0f};
    float O1[4] = {0.0f, 0.0f, 0.0f, 0.0f};
    const int vn = wn * 8 + grp;
    const unsigned* pr0 = sP + (wm * 32 + grp) * 140 + 2 * tig;
    const unsigned* pr1 = sP + (wm * 32 + grp + 8) * 140 + 2 * tig;
    const unsigned* pr2 = sP + (wm * 32 + grp + 16) * 140 + 2 * tig;
    const unsigned* pr3 = sP + (wm * 32 + grp + 24) * 140 + 2 * tig;

#pragma unroll
    for (int j = 0; j < 4; j++) {
        if (j >= nch) break;
        __syncthreads();                       // prev MMAs done: P and V[(j+1)&1] reusable
        if (j + 1 < nch) LOAD_V((j + 1) & 1, s_list[j + 1]);
        // store P chunk (packed-pair layout)
#pragma unroll
        for (int nj = 0; nj < 2; nj++)
#pragma unroll
            for (int b = 0; b < 2; b++) {
                int kl = wn * 16 + nj * 8 + 2 * tig + b;
                int pos = (kl >> 3) * 8 + (kl & 3) * 2 + ((kl >> 2) & 1);
#pragma unroll
                for (int rr = 0; rr < 4; rr++) {
                    int mi = rr >> 1, hh = rr & 1;
                    sP[rloc[rr] * 140 + pos] = f2tf(S[j][mi][nj][hh * 2 + b]);
                }
            }
        wait_pending((j + 1 < nch) ? 1 : 0);   // V[j] ready
        __syncthreads();
        const float* pV = sV + (j & 1) * 9216;
#pragma unroll
        for (int kk = 0; kk < 128; kk += 8) {
            uint2 u00 = *(const uint2*)(pr0 + kk);
            uint2 u01 = *(const uint2*)(pr1 + kk);
            uint2 u10 = *(const uint2*)(pr2 + kk);
            uint2 u11 = *(const uint2*)(pr3 + kk);
            unsigned af0[4] = {u00.x, u01.x, u00.y, u01.y};
            unsigned af1[4] = {u10.x, u11.x, u10.y, u11.y};
            unsigned bf[2] = { __float_as_uint(pV[(kk + tig) * 72 + vn]),
                               __float_as_uint(pV[(kk + tig + 4) * 72 + vn]) };
            MMA_TF32(O0, af0, bf);
            MMA_TF32(O1, af1, bf);
        }
    }
#undef LOAD_K
#undef LOAD_V

    // epilogue: normalize, tf32-round, write ctx
#pragma unroll
    for (int rr = 0; rr < 4; rr++) {
        int mi = rr >> 1, hh = rr & 1;
        const float* Osel = mi ? O1 : O0;
        float inv = s_rinv[rloc[rr]];
        float2 val;
        val.x = f2tff(Osel[hh * 2 + 0] * inv);
        val.y = f2tff(Osel[hh * 2 + 1] * inv);
        int d0 = wn * 8 + 2 * tig;
        *(float2*)(g_CTX + (size_t)(bt * SEQ + m0 + rloc[rr]) * DMODEL
                   + h * HDIM + d0) = val;
    }
}

// =============================================================================
extern "C" void kernel_launch(void* const* d_in, const int* in_sizes, int n_in,
                              void* d_out, int out_size)
{
    const float* x  = (const float*)d_in[0];
    const float* Wq = (const float*)d_in[1];
    const float* bq = (const float*)d_in[2];
    const float* Wk = (const float*)d_in[3];
    const float* bk = (const float*)d_in[4];
    const float* Wv = (const float*)d_in[5];
    const float* bv = (const float*)d_in[6];
    const float* Wo = (const float*)d_in[7];
    const float* bo = (const float*)d_in[8];
    const int* mods = (const int*)d_in[9];
    const int* nlp  = (n_in > 10) ? (const int*)d_in[10] : nullptr;
    float* out = (float*)d_out;

    cudaFuncSetAttribute(gemm768, cudaFuncAttributeMaxDynamicSharedMemorySize,
                         GD_BYTES);
    cudaFuncSetAttribute(attn_fused, cudaFuncAttributeMaxDynamicSharedMemorySize,
                         ATTN_SMEM_BYTES);

    gemm768<<<dim3(6, 128, 3), 128, GD_BYTES>>>(x, Wq, Wk, Wv, Wo,
                                                bq, bk, bv, bo, nullptr, 0);
    attn_fused<<<dim3(SEQ / 64, NBATCH), 512, ATTN_SMEM_BYTES>>>(mods, nlp);
    gemm768<<<dim3(6, 128, 1), 128, GD_BYTES>>>(x, Wq, Wk, Wv, Wo,
                                                bq, bk, bv, bo, out, 3);
}

// round 17
// speedup vs baseline: 2.2294x; 1.8240x over previous
#include <cuda_runtime.h>
#include <cuda_fp16.h>
#include <math.h>

// Problem constants
#define MROWS  16384   // B*T*S = 32*512
#define DMODEL 768
#define SEQ    512
#define NHEAD  12
#define HDIM   64
#define NBATCH 384     // (B*T)*H = 32*12

// ---------------- scratch (static device memory; no allocation) --------------
__device__ __half g_X16 [(size_t)MROWS * DMODEL];        // fp16 x, [m][k]
__device__ __half g_Wt16[(size_t)4 * DMODEL * DMODEL];   // fp16 W^T, [w][n][k]
__device__ __half g_Q16 [(size_t)NBATCH * SEQ * HDIM];   // [b*h][s][d] (pre-scaled)
__device__ __half g_K16 [(size_t)NBATCH * SEQ * HDIM];   // [b*h][s][d]
__device__ __half g_Vt16[(size_t)NBATCH * HDIM * SEQ];   // [b*h][d][s]
__device__ __half g_CTX16[(size_t)MROWS * DMODEL];       // [row][h*64+d]

// ---------------- helpers ----------------
__device__ __forceinline__ unsigned h2u(float a, float b) {
    __half2 t = __floats2half2_rn(a, b);
    return *(unsigned*)&t;
}
__device__ __forceinline__ void cp16(unsigned dst, const void* src) {
    asm volatile("cp.async.ca.shared.global [%0], [%1], 16;" :: "r"(dst), "l"(src));
}
__device__ __forceinline__ void wait_pending(int n) {
    if (n <= 0)      asm volatile("cp.async.wait_group 0;" ::: "memory");
    else if (n == 1) asm volatile("cp.async.wait_group 1;" ::: "memory");
    else if (n == 2) asm volatile("cp.async.wait_group 2;" ::: "memory");
    else if (n == 3) asm volatile("cp.async.wait_group 3;" ::: "memory");
    else             asm volatile("cp.async.wait_group 4;" ::: "memory");
}

#define MMA_F16(d, a, b)                                                           \
    asm volatile(                                                                  \
        "mma.sync.aligned.m16n8k16.row.col.f32.f16.f16.f32 "                       \
        "{%0,%1,%2,%3}, {%4,%5,%6,%7}, {%8,%9}, {%0,%1,%2,%3};"                    \
        : "+f"((d)[0]), "+f"((d)[1]), "+f"((d)[2]), "+f"((d)[3])                   \
        : "r"((a)[0]), "r"((a)[1]), "r"((a)[2]), "r"((a)[3]),                      \
          "r"((b)[0]), "r"((b)[1]))

// =============================================================================
// prep: x -> fp16 [m][k]; W -> fp16 transposed [n][k] x4 (tiled transpose).
// =============================================================================
__global__ __launch_bounds__(256) void prep_x(const float* __restrict__ x)
{
    int i = blockIdx.x * 256 + threadIdx.x;      // 8 elems per thread
    const float4 a = ((const float4*)x)[i * 2];
    const float4 b = ((const float4*)x)[i * 2 + 1];
    uint4 u;
    u.x = h2u(a.x, a.y); u.y = h2u(a.z, a.w);
    u.z = h2u(b.x, b.y); u.w = h2u(b.z, b.w);
    ((uint4*)g_X16)[i] = u;
}

__global__ void prep_w(const float* __restrict__ Wq, const float* __restrict__ Wk,
                       const float* __restrict__ Wv, const float* __restrict__ Wo)
{
    __shared__ float t[32][33];
    const int wsel = blockIdx.z;
    const float* __restrict__ in =
        (wsel == 0) ? Wq : (wsel == 1) ? Wk : (wsel == 2) ? Wv : Wo;
    __half* out = g_Wt16 + (size_t)wsel * DMODEL * DMODEL;
    const int n0 = blockIdx.x * 32, k0 = blockIdx.y * 32;
    const int tx = threadIdx.x, ty = threadIdx.y;
#pragma unroll
    for (int j = 0; j < 4; j++)
        t[ty + j * 8][tx] = in[(size_t)(k0 + ty + j * 8) * DMODEL + n0 + tx];
    __syncthreads();
#pragma unroll
    for (int j = 0; j < 4; j++)
        out[(size_t)(n0 + ty + j * 8) * DMODEL + k0 + tx] =
            __float2half_rn(t[tx][ty + j * 8]);
}

// scatter for projection GEMM epilogues
__device__ __forceinline__ void scatter(int mode, int m, int n, float v,
                                        float* __restrict__ out) {
    int bt = m >> 9, s = m & 511;
    int h = n >> 6, d = n & 63;
    if (mode == 0) {
        g_Q16[((size_t)(bt * NHEAD + h) * SEQ + s) * HDIM + d] = __float2half_rn(v * 0.125f);
    } else if (mode == 1) {
        g_K16[((size_t)(bt * NHEAD + h) * SEQ + s) * HDIM + d] = __float2half_rn(v);
    } else if (mode == 2) {
        g_Vt16[((size_t)(bt * NHEAD + h) * HDIM + d) * SEQ + s] = __float2half_rn(v);
    } else {
        out[(size_t)m * DMODEL + n] = v;
    }
}

extern __shared__ unsigned dsm[];

// =============================================================================
// 128x128 fp16-MMA GEMM over K=768. 128 threads = 4 warps, warp grid 2x2,
// warp tile 64x64, k-chunk 32, 4-stage cp.async pipeline. QKV via gridDim.z.
// Stage (halves): A [m][k] stride 40 (5120 h), B [n][k] stride 40 (5120 h).
// =============================================================================
#define GST_H    10240
#define GD_BYTES (4 * GST_H * 2)   // 81920

__global__ __launch_bounds__(128, 2) void gemm768(
    const float* __restrict__ bq, const float* __restrict__ bk,
    const float* __restrict__ bv, const float* __restrict__ bo,
    float* __restrict__ out, int base_mode)
{
    __half* smH = (__half*)dsm;
    const int mode = base_mode + blockIdx.z;
    const float* __restrict__ bias =
        (mode == 0) ? bq : (mode == 1) ? bk : (mode == 2) ? bv : bo;
    const __half* __restrict__ A = (mode == 3) ? g_CTX16 : g_X16;
    const __half* __restrict__ W = g_Wt16 + (size_t)mode * DMODEL * DMODEL;

    const int tid  = threadIdx.x;
    const int lane = tid & 31, warp = tid >> 5;
    const int wm = warp & 1, wn = warp >> 1;     // 2 x 2 warp grid
    const int grp = lane >> 2, tig = lane & 3;
    const int m0 = blockIdx.y * 128;
    const int n0 = blockIdx.x * 128;

    const unsigned s_u32 = (unsigned)__cvta_generic_to_shared(dsm);

    float acc[4][8][4];
#pragma unroll
    for (int i = 0; i < 4; i++)
#pragma unroll
        for (int j = 0; j < 8; j++)
#pragma unroll
            for (int e = 0; e < 4; e++) acc[i][j][e] = 0.0f;

#define G_LOAD(st, k0)                                                            \
    {                                                                             \
        _Pragma("unroll")                                                         \
        for (int rep = 0; rep < 4; rep++) {                                       \
            int t = rep * 128 + tid;                                              \
            int r = t >> 2, c8 = (t & 3) * 8;                                     \
            cp16(s_u32 + (unsigned)(((st) * GST_H + r * 40 + c8) * 2),            \
                 A + (size_t)(m0 + r) * DMODEL + (k0) + c8);                      \
        }                                                                         \
        _Pragma("unroll")                                                         \
        for (int rep = 0; rep < 4; rep++) {                                       \
            int t = rep * 128 + tid;                                              \
            int r = t >> 2, c8 = (t & 3) * 8;                                     \
            cp16(s_u32 + (unsigned)(((st) * GST_H + 5120 + r * 40 + c8) * 2),     \
                 W + (size_t)(n0 + r) * DMODEL + (k0) + c8);                      \
        }                                                                         \
        asm volatile("cp.async.commit_group;" ::: "memory");                      \
    }

    G_LOAD(0, 0);
    G_LOAD(1, 32);
    G_LOAD(2, 64);

    for (int ci = 0; ci < 24; ci++) {
        asm volatile("cp.async.wait_group 2;" ::: "memory");
        __syncthreads();
        if (ci + 3 < 24) G_LOAD((ci + 3) & 3, (ci + 3) * 32);

        const __half* pA = smH + (ci & 3) * GST_H;
        const __half* pB = pA + 5120;
#pragma unroll
        for (int s = 0; s < 2; s++) {
            const int ks = s * 16;
            unsigned af[4][4], bf[8][2];
#pragma unroll
            for (int mi = 0; mi < 4; mi++) {
                const __half* pa = pA + (wm * 64 + mi * 16 + grp) * 40 + ks + 2 * tig;
                af[mi][0] = *(const unsigned*)pa;
                af[mi][1] = *(const unsigned*)(pa + 8 * 40);
                af[mi][2] = *(const unsigned*)(pa + 8);
                af[mi][3] = *(const unsigned*)(pa + 8 * 40 + 8);
            }
#pragma unroll
            for (int nj = 0; nj < 8; nj++) {
                const __half* pb = pB + (wn * 64 + nj * 8 + grp) * 40 + ks + 2 * tig;
                bf[nj][0] = *(const unsigned*)pb;
                bf[nj][1] = *(const unsigned*)(pb + 8);
            }
#pragma unroll
            for (int mi = 0; mi < 4; mi++)
#pragma unroll
                for (int nj = 0; nj < 8; nj++)
                    MMA_F16(acc[mi][nj], af[mi], bf[nj]);
        }
    }
#undef G_LOAD

#pragma unroll
    for (int mi = 0; mi < 4; mi++) {
        int r0 = m0 + wm * 64 + mi * 16 + grp;
#pragma unroll
        for (int nj = 0; nj < 8; nj++) {
            int c0 = n0 + wn * 64 + nj * 8 + tig * 2;
            scatter(mode, r0,     c0,     acc[mi][nj][0] + bias[c0],     out);
            scatter(mode, r0,     c0 + 1, acc[mi][nj][1] + bias[c0 + 1], out);
            scatter(mode, r0 + 8, c0,     acc[mi][nj][2] + bias[c0],     out);
            scatter(mode, r0 + 8, c0 + 1, acc[mi][nj][3] + bias[c0 + 1], out);
        }
    }
}

// =============================================================================
// Fused attention (fp16 operands): block = (head-batch, 64 q rows), 512 thr.
// Chunk skipping, all-K upfront prefetch, double-buffered V.
// Half-offsets: Q [q][d] stride 72 (4608h); K 4 bufs [s][d] stride 72 (9216h ea);
// overlay: P [q][key] stride 136 (8704h), Vt 2 bufs [d][s] stride 136 (8704h ea).
// =============================================================================
#define HQ    0
#define HK    4608
#define HP    4608
#define HV    13312
#define WMODS 20736      // word offsets (dsm base)
#define WRED  21248
#define WRMAX 22272
#define WRINV 22336
#define WCMSK 22400
#define WRSUM 22404
#define WLIST 22406
#define WNCH  22410
#define ATTN_SMEM_BYTES (22416 * 4)   // 89664

__device__ __forceinline__ int modbit(int m) {
    return (m == -1) ? 4 : (m == 0) ? 1 : (m == 1) ? 2 : 8;
}

__global__ __launch_bounds__(512, 1) void attn_fused(
    const int* __restrict__ mods, const int* __restrict__ nlp)
{
    __half* smH      = (__half*)dsm;
    __half* sQ       = smH + HQ;
    __half* sK       = smH + HK;
    __half* sP       = smH + HP;
    __half* sV       = smH + HV;
    int*    s_mods   = (int*)(dsm + WMODS);
    float*  s_red    = (float*)(dsm + WRED);
    float*  s_rmax   = (float*)(dsm + WRMAX);
    float*  s_rinv   = (float*)(dsm + WRINV);
    int*    s_cmsk   = (int*)(dsm + WCMSK);
    int*    s_rsum   = (int*)(dsm + WRSUM);
    int*    s_list   = (int*)(dsm + WLIST);
    int*    s_nch    = (int*)(dsm + WNCH);

    const int tid  = threadIdx.x;
    const int lane = tid & 31, w = tid >> 5;
    const int grp  = lane >> 2, tig = lane & 3;
    const int wm = w & 1, wn = w >> 1;          // 2 x 8 warp grid
    const int batch = blockIdx.y;
    const int m0 = blockIdx.x * 64;
    const int bt = batch / NHEAD, h = batch % NHEAD;
    const int nlat = nlp ? *nlp : 32;

    const __half* __restrict__ Qp  = g_Q16  + (size_t)batch * SEQ * HDIM;
    const __half* __restrict__ Kp  = g_K16  + (size_t)batch * SEQ * HDIM;
    const __half* __restrict__ Vtp = g_Vt16 + (size_t)batch * HDIM * SEQ;
    const unsigned smem_u32 = (unsigned)__cvta_generic_to_shared(dsm);

    int my_mod = mods[tid];
    s_mods[tid] = my_mod;
    if (tid < 8) ((int*)(dsm + WCMSK))[tid] = 0;

    // Q tile via cp.async (group 0): 64 rows x 64 halves = 512 x 16B
    {
        int r = tid >> 3, c8 = (tid & 7) * 8;
        cp16(smem_u32 + (unsigned)((HQ + r * 72 + c8) * 2),
             Qp + (size_t)(m0 + r) * HDIM + c8);
        asm volatile("cp.async.commit_group;" ::: "memory");
    }
    __syncthreads();

    // ---------------- chunk analysis (warp-parallel) ----------------
    {
        int mb = modbit(my_mod);
#pragma unroll
        for (int d = 16; d >= 1; d >>= 1)
            mb |= __shfl_xor_sync(0xffffffffu, mb, d);
        if (lane == 0) atomicOr(&s_cmsk[w >> 2], mb);
        if (tid < 64) {
            int rg = m0 + tid;
            int rb = (rg < nlat) ? 0 : modbit(s_mods[rg]);
            int rl = (rg < nlat) ? 1 : 0;
#pragma unroll
            for (int d = 16; d >= 1; d >>= 1) {
                rb |= __shfl_xor_sync(0xffffffffu, rb, d);
                rl |= __shfl_xor_sync(0xffffffffu, rl, d);
            }
            if (lane == 0) { atomicOr(&s_rsum[0], rb); atomicOr(&s_rsum[1], rl); }
        }
    }
    __syncthreads();
    if (tid == 0) {
        int n = 0;
        for (int c = 0; c < 4; c++)
            if (s_rsum[1] || (s_rsum[0] & s_cmsk[c])) s_list[n++] = c;
        *s_nch = n;
    }
    __syncthreads();
    const int nch = *s_nch;

    // issue ALL needed K-chunk loads (128 keys x 64 halves = 1024 x 16B each)
#define LOAD_K(buf, c)                                                            \
    {                                                                             \
        _Pragma("unroll")                                                         \
        for (int rep = 0; rep < 2; rep++) {                                       \
            int idx = rep * 512 + tid;                                            \
            int r = idx >> 3, c8 = (idx & 7) * 8;                                 \
            cp16(smem_u32 + (unsigned)((HK + (buf) * 9216 + r * 72 + c8) * 2),    \
                 Kp + (size_t)((c) * 128 + r) * HDIM + c8);                       \
        }                                                                         \
        asm volatile("cp.async.commit_group;" ::: "memory");                      \
    }
#define LOAD_V(buf, c)                                                            \
    {                                                                             \
        _Pragma("unroll")                                                         \
        for (int rep = 0; rep < 2; rep++) {                                       \
            int idx = rep * 512 + tid;                                            \
            int r = idx >> 4, c8 = (idx & 15) * 8;                                \
            cp16(smem_u32 + (unsigned)((HV + (buf) * 8704 + r * 136 + c8) * 2),   \
                 Vtp + (size_t)r * SEQ + (c) * 128 + c8);                         \
        }                                                                         \
        asm volatile("cp.async.commit_group;" ::: "memory");                      \
    }
    for (int j = 0; j < nch; j++) LOAD_K(j, s_list[j]);

    float S[4][2][2][4];
#pragma unroll
    for (int c = 0; c < 4; c++)
#pragma unroll
        for (int i = 0; i < 2; i++)
#pragma unroll
            for (int j = 0; j < 2; j++)
#pragma unroll
                for (int e = 0; e < 4; e++) S[c][i][j][e] = 0.0f;

    // ---------------- phase 1: S = Q @ K^T (needed chunks only) -------------
#pragma unroll
    for (int j = 0; j < 4; j++) {
        if (j >= nch) break;
        wait_pending(nch - 1 - j);   // Q(group0) + K0..Kj complete
        __syncthreads();
        const __half* pK = sK + j * 9216;
#pragma unroll
        for (int s = 0; s < 4; s++) {
            const int ks = s * 16;
            unsigned af[2][4], bf[2][2];
#pragma unroll
            for (int mi = 0; mi < 2; mi++) {
                const __half* pa = sQ + (wm * 32 + mi * 16 + grp) * 72 + ks + 2 * tig;
                af[mi][0] = *(const unsigned*)pa;
                af[mi][1] = *(const unsigned*)(pa + 8 * 72);
                af[mi][2] = *(const unsigned*)(pa + 8);
                af[mi][3] = *(const unsigned*)(pa + 8 * 72 + 8);
            }
#pragma unroll
            for (int nj = 0; nj < 2; nj++) {
                const __half* pb = pK + (wn * 16 + nj * 8 + grp) * 72 + ks + 2 * tig;
                bf[nj][0] = *(const unsigned*)pb;
                bf[nj][1] = *(const unsigned*)(pb + 8);
            }
#pragma unroll
            for (int mi = 0; mi < 2; mi++)
#pragma unroll
                for (int nj = 0; nj < 2; nj++)
                    MMA_F16(S[j][mi][nj], af[mi], bf[nj]);
        }
    }
#undef LOAD_K

    // ---------------- mask + softmax (needed chunks only) -------------------
    int rloc[4]; int mq[4]; bool lat[4]; float lm[4];
#pragma unroll
    for (int rr = 0; rr < 4; rr++) {
        int mi = rr >> 1, hh = rr & 1;
        rloc[rr] = wm * 32 + mi * 16 + hh * 8 + grp;
        int rg = m0 + rloc[rr];
        lat[rr] = (rg < nlat);
        mq[rr] = s_mods[rg];
        lm[rr] = -3.0e38f;
    }
#pragma unroll
    for (int j = 0; j < 4; j++) {
        if (j >= nch) break;
        int c = s_list[j];
#pragma unroll
        for (int nj = 0; nj < 2; nj++) {
            int k0 = c * 128 + wn * 16 + nj * 8 + 2 * tig;
            int md0 = s_mods[k0], md1 = s_mods[k0 + 1];
#pragma unroll
            for (int rr = 0; rr < 4; rr++) {
                int mi = rr >> 1, hh = rr & 1;
                float& s0 = S[j][mi][nj][hh * 2 + 0];
                float& s1 = S[j][mi][nj][hh * 2 + 1];
                if (!(lat[rr] || mq[rr] == md0)) s0 = -3.0e38f;
                if (!(lat[rr] || mq[rr] == md1)) s1 = -3.0e38f;
                lm[rr] = fmaxf(lm[rr], fmaxf(s0, s1));
            }
        }
    }
#pragma unroll
    for (int rr = 0; rr < 4; rr++) {
        lm[rr] = fmaxf(lm[rr], __shfl_xor_sync(0xffffffffu, lm[rr], 1));
        lm[rr] = fmaxf(lm[rr], __shfl_xor_sync(0xffffffffu, lm[rr], 2));
    }
    if (tig == 0) {
#pragma unroll
        for (int rr = 0; rr < 4; rr++) s_red[w * 64 + rloc[rr]] = lm[rr];
    }
    __syncthreads();

    // prefetch first V chunk (K buffers consumed; overlaps softmax)
    LOAD_V(0, s_list[0]);

    if (tid < 64) {
        int wsel = tid >> 5;
        float m = -3.0e38f;
#pragma unroll
        for (int j = 0; j < 8; j++) m = fmaxf(m, s_red[(2 * j + wsel) * 64 + tid]);
        s_rmax[tid] = m;
    }
    __syncthreads();

    float rm[4], ls[4];
#pragma unroll
    for (int rr = 0; rr < 4; rr++) { rm[rr] = s_rmax[rloc[rr]]; ls[rr] = 0.0f; }
#pragma unroll
    for (int j = 0; j < 4; j++) {
        if (j >= nch) break;
#pragma unroll
        for (int nj = 0; nj < 2; nj++)
#pragma unroll
            for (int rr = 0; rr < 4; rr++) {
                int mi = rr >> 1, hh = rr & 1;
                float& s0 = S[j][mi][nj][hh * 2 + 0];
                float& s1 = S[j][mi][nj][hh * 2 + 1];
                s0 = __expf(s0 - rm[rr]);
                s1 = __expf(s1 - rm[rr]);
                ls[rr] += s0 + s1;
            }
    }
#pragma unroll
    for (int rr = 0; rr < 4; rr++) {
        ls[rr] += __shfl_xor_sync(0xffffffffu, ls[rr], 1);
        ls[rr] += __shfl_xor_sync(0xffffffffu, ls[rr], 2);
    }
    if (tig == 0) {
#pragma unroll
        for (int rr = 0; rr < 4; rr++) s_red[w * 64 + rloc[rr]] = ls[rr];
    }
    __syncthreads();
    if (tid < 64) {
        int wsel = tid >> 5;
        float s = 0.0f;
#pragma unroll
        for (int j = 0; j < 8; j++) s += s_red[(2 * j + wsel) * 64 + tid];
        s_rinv[tid] = 1.0f / s;
    }

    // ---------------- phase 2: O = P @ V (double-buffered V) ---------------
    float O0[4] = {0.0f, 0.0f, 0.0f, 0.0f};
    float O1[4] = {0.0f, 0.0f, 0.0f, 0.0f};

#pragma unroll
    for (int j = 0; j < 4; j++) {
        if (j >= nch) break;
        __syncthreads();                       // prev MMAs done; V[(j+1)&1] reusable
        if (j + 1 < nch) LOAD_V((j + 1) & 1, s_list[j + 1]);
        // store P chunk as fp16 pairs: key pair (2tig, 2tig+1) -> one .u32 store
#pragma unroll
        for (int nj = 0; nj < 2; nj++)
#pragma unroll
            for (int rr = 0; rr < 4; rr++) {
                int mi = rr >> 1, hh = rr & 1;
                unsigned pk = h2u(S[j][mi][nj][hh * 2 + 0], S[j][mi][nj][hh * 2 + 1]);
                *(unsigned*)(sP + rloc[rr] * 136 + wn * 16 + nj * 8 + 2 * tig) = pk;
            }
        wait_pending((j + 1 < nch) ? 1 : 0);   // V[j] ready
        __syncthreads();
        const __half* pV = sV + (j & 1) * 8704;
#pragma unroll
        for (int s = 0; s < 8; s++) {
            const int ks = s * 16;
            unsigned af[2][4], bf[2];
#pragma unroll
            for (int mi = 0; mi < 2; mi++) {
                const __half* pa = sP + (wm * 32 + mi * 16 + grp) * 136 + ks + 2 * tig;
                af[mi][0] = *(const unsigned*)pa;
                af[mi][1] = *(const unsigned*)(pa + 8 * 136);
                af[mi][2] = *(const unsigned*)(pa + 8);
                af[mi][3] = *(const unsigned*)(pa + 8 * 136 + 8);
            }
            const __half* pb = pV + (wn * 8 + grp) * 136 + ks + 2 * tig;
            bf[0] = *(const unsigned*)pb;
            bf[1] = *(const unsigned*)(pb + 8);
            MMA_F16(O0, af[0], bf);
            MMA_F16(O1, af[1], bf);
        }
    }
#undef LOAD_V

    // epilogue: normalize, fp16-round, write ctx
#pragma unroll
    for (int rr = 0; rr < 4; rr++) {
        int mi = rr >> 1, hh = rr & 1;
        const float* Osel = mi ? O1 : O0;
        float inv = s_rinv[rloc[rr]];
        unsigned pk = h2u(Osel[hh * 2 + 0] * inv, Osel[hh * 2 + 1] * inv);
        int d0 = wn * 8 + 2 * tig;
        *(unsigned*)(g_CTX16 + (size_t)(bt * SEQ + m0 + rloc[rr]) * DMODEL
                     + h * HDIM + d0) = pk;
    }
}

// =============================================================================
extern "C" void kernel_launch(void* const* d_in, const int* in_sizes, int n_in,
                              void* d_out, int out_size)
{
    const float* x  = (const float*)d_in[0];
    const float* Wq = (const float*)d_in[1];
    const float* bq = (const float*)d_in[2];
    const float* Wk = (const float*)d_in[3];
    const float* bk = (const float*)d_in[4];
    const float* Wv = (const float*)d_in[5];
    const float* bv = (const float*)d_in[6];
    const float* Wo = (const float*)d_in[7];
    const float* bo = (const float*)d_in[8];
    const int* mods = (const int*)d_in[9];
    const int* nlp  = (n_in > 10) ? (const int*)d_in[10] : nullptr;
    float* out = (float*)d_out;

    cudaFuncSetAttribute(gemm768, cudaFuncAttributeMaxDynamicSharedMemorySize,
                         GD_BYTES);
    cudaFuncSetAttribute(attn_fused, cudaFuncAttributeMaxDynamicSharedMemorySize,
                         ATTN_SMEM_BYTES);

    prep_x<<<(MROWS * DMODEL) / (256 * 8), 256>>>(x);
    prep_w<<<dim3(24, 24, 4), dim3(32, 8)>>>(Wq, Wk, Wv, Wo);
    gemm768<<<dim3(6, 128, 3), 128, GD_BYTES>>>(bq, bk, bv, bo, nullptr, 0);
    attn_fused<<<dim3(SEQ / 64, NBATCH), 512, ATTN_SMEM_BYTES>>>(mods, nlp);
    gemm768<<<dim3(6, 128, 1), 128, GD_BYTES>>>(bq, bk, bv, bo, out, 3);
}